// round 13
// baseline (speedup 1.0000x reference)
#include <cuda_runtime.h>
#include <cuda_bf16.h>
#include <cstdint>

#define LRELU_ALPHA 0.2f

constexpr int N    = 8192;
constexpr int KIN  = 512;
constexpr int OUTD = 256;
constexpr int W257 = OUTD + 1;
constexpr int NCH  = 512;
constexpr int CHL  = N / NCH;    // 16

// ---------------- scratch (device globals; no allocation) ----------------
__device__ float g_h[N * OUTD];
__device__ float g_s2p[2 * N];
__device__ float g_key[N];
__device__ int   g_idx[N];
__device__ float g_cs1[W257 * NCH];          // chunk sums [k][c]
__device__ float g_cs2[W257 * NCH];
__device__ float g_co1t[NCH * W257];         // exclusive suffix offsets, [c][k]
__device__ float g_co2t[NCH * W257];         // exclusive prefix offsets, [c][k]
__device__ float g_SE[(N + 1) * W257];       // within-chunk partial suffix
__device__ float g_P2[(N + 1) * W257];       // within-chunk partial prefix

__device__ __forceinline__ uint32_t smem_u32(const void* p) {
    uint32_t a;
    asm("{ .reg .u64 t; cvta.to.shared.u64 t, %1; cvt.u32.u64 %0, t; }" : "=r"(a) : "l"(p));
    return a;
}

// ==================== fused GEMM: h = x @ W^T, + s2 partials ====================
constexpr int SSTR = 40;

__device__ __forceinline__ void ldsm_x4(uint32_t (&r)[4], uint32_t addr) {
    asm volatile("ldmatrix.sync.aligned.m8n8.x4.shared.b16 {%0,%1,%2,%3}, [%4];"
                 : "=r"(r[0]), "=r"(r[1]), "=r"(r[2]), "=r"(r[3]) : "r"(addr));
}
__device__ __forceinline__ void mma_bf16(float (&c)[4], const uint32_t (&a)[4],
                                         uint32_t b0, uint32_t b1) {
    asm volatile(
        "mma.sync.aligned.m16n8k16.row.col.f32.bf16.bf16.f32 "
        "{%0,%1,%2,%3}, {%4,%5,%6,%7}, {%8,%9}, {%0,%1,%2,%3};"
        : "+f"(c[0]), "+f"(c[1]), "+f"(c[2]), "+f"(c[3])
        : "r"(a[0]), "r"(a[1]), "r"(a[2]), "r"(a[3]), "r"(b0), "r"(b1));
}
__device__ __forceinline__ void cvt_hilo(float4 v, uint2& hi, uint2& lo) {
    __nv_bfloat16 h0 = __float2bfloat16(v.x), h1 = __float2bfloat16(v.y);
    __nv_bfloat16 h2 = __float2bfloat16(v.z), h3 = __float2bfloat16(v.w);
    __nv_bfloat16 l0 = __float2bfloat16(v.x - __bfloat162float(h0));
    __nv_bfloat16 l1 = __float2bfloat16(v.y - __bfloat162float(h1));
    __nv_bfloat16 l2 = __float2bfloat16(v.z - __bfloat162float(h2));
    __nv_bfloat16 l3 = __float2bfloat16(v.w - __bfloat162float(h3));
    __nv_bfloat162 p0(h0, h1), p1(h2, h3), q0(l0, l1), q1(l2, l3);
    hi.x = *reinterpret_cast<uint32_t*>(&p0);
    hi.y = *reinterpret_cast<uint32_t*>(&p1);
    lo.x = *reinterpret_cast<uint32_t*>(&q0);
    lo.y = *reinterpret_cast<uint32_t*>(&q1);
}

__global__ void __launch_bounds__(256, 1) gemm_fused_kernel(
    const float* __restrict__ x, const float* __restrict__ Wm,
    const float* __restrict__ a2) {
    __shared__ __nv_bfloat16 sAh[128 * SSTR];
    __shared__ __nv_bfloat16 sAl[128 * SSTR];
    __shared__ __nv_bfloat16 sBh[128 * SSTR];
    __shared__ __nv_bfloat16 sBl[128 * SSTR];

    const int tid  = threadIdx.x;
    const int wid  = tid >> 5;
    const int lane = tid & 31;
    const int wm   = wid & 1;
    const int wn   = wid >> 1;
    const int nb   = blockIdx.x;
    const int m0   = blockIdx.y * 128;
    const int n0   = nb * 128;

    const uint32_t bAh = smem_u32(sAh);
    const uint32_t bAl = smem_u32(sAl);
    const uint32_t bBh = smem_u32(sBh);
    const uint32_t bBl = smem_u32(sBl);

    int srow[4], scol[4];
    #pragma unroll
    for (int i = 0; i < 4; ++i) {
        int lin = i * 256 + tid;
        srow[i] = lin >> 3;
        scol[i] = (lin & 7) * 4;
    }

    float acc[4][4][4] = {};
    float4 pvx[4], pvw[4];

    #pragma unroll
    for (int i = 0; i < 4; ++i) {
        pvx[i] = *(const float4*)(x  + (size_t)(m0 + srow[i]) * KIN + scol[i]);
        pvw[i] = *(const float4*)(Wm + (size_t)(n0 + srow[i]) * KIN + scol[i]);
    }

    for (int kc = 0; kc < KIN / 32; ++kc) {
        #pragma unroll
        for (int i = 0; i < 4; ++i) {
            uint2 hi, lo;
            int so = srow[i] * SSTR + scol[i];
            cvt_hilo(pvx[i], hi, lo);
            *(uint2*)(sAh + so) = hi;
            *(uint2*)(sAl + so) = lo;
            cvt_hilo(pvw[i], hi, lo);
            *(uint2*)(sBh + so) = hi;
            *(uint2*)(sBl + so) = lo;
        }
        __syncthreads();

        if (kc + 1 < KIN / 32) {
            int kb = (kc + 1) * 32;
            #pragma unroll
            for (int i = 0; i < 4; ++i) {
                pvx[i] = *(const float4*)(x  + (size_t)(m0 + srow[i]) * KIN + kb + scol[i]);
                pvw[i] = *(const float4*)(Wm + (size_t)(n0 + srow[i]) * KIN + kb + scol[i]);
            }
        }

        #pragma unroll
        for (int kk = 0; kk < 2; ++kk) {
            uint32_t ah[4][4], al[4][4], bh[2][4], bl[2][4];
            #pragma unroll
            for (int mt = 0; mt < 4; ++mt) {
                uint32_t off = (uint32_t)((wm * 64 + mt * 16 + (lane & 15)) * SSTR
                                          + kk * 16 + (lane >> 4) * 8) * 2;
                ldsm_x4(ah[mt], bAh + off);
                ldsm_x4(al[mt], bAl + off);
            }
            #pragma unroll
            for (int ntp = 0; ntp < 2; ++ntp) {
                uint32_t off = (uint32_t)((wn * 32 + ntp * 16 + ((lane >> 4) * 8) + (lane & 7)) * SSTR
                                          + kk * 16 + ((lane >> 3) & 1) * 8) * 2;
                ldsm_x4(bh[ntp], bBh + off);
                ldsm_x4(bl[ntp], bBl + off);
            }
            #pragma unroll
            for (int mt = 0; mt < 4; ++mt)
                #pragma unroll
                for (int nf = 0; nf < 4; ++nf) {
                    uint32_t bh0 = bh[nf >> 1][(nf & 1) * 2], bh1 = bh[nf >> 1][(nf & 1) * 2 + 1];
                    uint32_t bl0 = bl[nf >> 1][(nf & 1) * 2], bl1 = bl[nf >> 1][(nf & 1) * 2 + 1];
                    mma_bf16(acc[mt][nf], ah[mt], bh0, bh1);
                    mma_bf16(acc[mt][nf], ah[mt], bl0, bl1);
                    mma_bf16(acc[mt][nf], al[mt], bh0, bh1);
                }
        }
        __syncthreads();
    }

    #pragma unroll
    for (int mt = 0; mt < 4; ++mt)
        #pragma unroll
        for (int nf = 0; nf < 4; ++nf) {
            int row0 = m0 + wm * 64 + mt * 16 + (lane >> 2);
            int col  = n0 + wn * 32 + nf * 8 + (lane & 3) * 2;
            *(float2*)&g_h[(size_t)row0 * OUTD + col] =
                make_float2(acc[mt][nf][0], acc[mt][nf][1]);
            *(float2*)&g_h[(size_t)(row0 + 8) * OUTD + col] =
                make_float2(acc[mt][nf][2], acc[mt][nf][3]);
        }

    // s2 partial reduction over this CTA's 128 columns
    float* red = (float*)sAh;
    #pragma unroll
    for (int mt = 0; mt < 4; ++mt) {
        float r2a = 0.f, r2b = 0.f;
        #pragma unroll
        for (int nf = 0; nf < 4; ++nf) {
            int col = n0 + wn * 32 + nf * 8 + (lane & 3) * 2;
            float a20 = a2[col], a21 = a2[col + 1];
            r2a += acc[mt][nf][0] * a20 + acc[mt][nf][1] * a21;
            r2b += acc[mt][nf][2] * a20 + acc[mt][nf][3] * a21;
        }
        #pragma unroll
        for (int o = 1; o <= 2; o <<= 1) {
            r2a += __shfl_xor_sync(0xFFFFFFFFu, r2a, o);
            r2b += __shfl_xor_sync(0xFFFFFFFFu, r2b, o);
        }
        if ((lane & 3) == 0) {
            int row = wm * 64 + mt * 16 + (lane >> 2);
            red[row * 4 + wn]       = r2a;
            red[(row + 8) * 4 + wn] = r2b;
        }
    }
    __syncthreads();
    if (tid < 128) {
        float s2 = red[tid * 4] + red[tid * 4 + 1] + red[tid * 4 + 2] + red[tid * 4 + 3];
        g_s2p[nb * N + m0 + tid] = s2;
    }
}

// ==================== self-contained sort: s1 GEMV + 8-CTA cluster bitonic ====================
#define CLUSTER_SYNC() do {                                             \
    asm volatile("barrier.cluster.arrive.aligned;" ::: "memory");       \
    asm volatile("barrier.cluster.wait.aligned;" ::: "memory");         \
} while (0)

__device__ __forceinline__ unsigned long long dsmem_ld64(uint32_t laddr, uint32_t rank) {
    uint32_t ra;
    unsigned long long v;
    asm volatile("mapa.shared::cluster.u32 %0, %1, %2;" : "=r"(ra) : "r"(laddr), "r"(rank));
    asm volatile("ld.shared::cluster.u64 %0, [%1];" : "=l"(v) : "r"(ra) : "memory");
    return v;
}
__device__ __forceinline__ unsigned long long u64min(unsigned long long a, unsigned long long b) { return a < b ? a : b; }
__device__ __forceinline__ unsigned long long u64max(unsigned long long a, unsigned long long b) { return a < b ? b : a; }

__global__ void __launch_bounds__(1024, 1) __cluster_dims__(8, 1, 1) sort_kernel(
    const float* __restrict__ x, const float* __restrict__ Wm,
    const float* __restrict__ a1v) {
    __shared__ unsigned long long sbuf[2][1024];
    __shared__ float sw1[KIN];
    const int t = threadIdx.x;
    uint32_t rank;
    asm("mov.u32 %0, %%cluster_ctarank;" : "=r"(rank));
    const int ge = (int)rank * 1024 + t;

    // w1 = W^T a1 (each CTA redundantly; coalesced W reads)
    if (t < KIN) {
        float acc = 0.f;
        #pragma unroll 4
        for (int o = 0; o < OUTD; ++o)
            acc += Wm[(size_t)o * KIN + t] * a1v[o];
        sw1[t] = acc;
    }
    __syncthreads();

    // s1[ge] = x[ge] . w1
    const float4* xr = (const float4*)(x + (size_t)ge * KIN);
    float s1 = 0.f;
    #pragma unroll 4
    for (int j = 0; j < KIN / 4; ++j) {
        float4 v = xr[j];
        s1 += v.x * sw1[4 * j] + v.y * sw1[4 * j + 1]
            + v.z * sw1[4 * j + 2] + v.w * sw1[4 * j + 3];
    }

    uint32_t u = __float_as_uint(s1);
    u ^= (u & 0x80000000u) ? 0xFFFFFFFFu : 0x80000000u;
    unsigned long long own = ((unsigned long long)u << 13) | (unsigned)ge;

    // sizes 2..32: pure shuffles
    #pragma unroll
    for (int size = 2; size <= 32; size <<= 1) {
        bool up = ((ge & size) == 0);
        #pragma unroll
        for (int stride = size >> 1; stride >= 1; stride >>= 1) {
            unsigned long long p = __shfl_xor_sync(0xFFFFFFFFu, own, stride);
            bool keepmin = (((t & stride) == 0) == up);
            own = keepmin ? u64min(own, p) : u64max(own, p);
        }
    }
    int cur = 0;
    unsigned long long* s = sbuf[0];
    s[t] = own;
    __syncthreads();

    // sizes 64..1024: smem strides 32..512, shuffles below
    for (int size = 64; size <= 1024; size <<= 1) {
        for (int stride = size >> 1; stride >= 32; stride >>= 1) {
            if (t < 512) {
                int a = ((t & ~(stride - 1)) << 1) | (t & (stride - 1));
                int b = a + stride;
                bool up = ((((int)rank * 1024 + a) & size) == 0);
                unsigned long long xx = s[a], yy = s[b];
                if ((xx > yy) == up) { s[a] = yy; s[b] = xx; }
            }
            __syncthreads();
        }
        own = s[t];
        bool up = ((ge & size) == 0);
        #pragma unroll
        for (int stride = 16; stride >= 1; stride >>= 1) {
            unsigned long long p = __shfl_xor_sync(0xFFFFFFFFu, own, stride);
            bool keepmin = (((t & stride) == 0) == up);
            own = keepmin ? u64min(own, p) : u64max(own, p);
        }
        s[t] = own;
        __syncthreads();
    }

    CLUSTER_SYNC();   // all CTAs' buffer 0 valid

    const uint32_t addr0 = smem_u32(&sbuf[0][t]);
    const uint32_t addr1 = smem_u32(&sbuf[1][t]);
    for (int size = 2048; size <= 8192; size <<= 1) {
        bool up = ((ge & size) == 0);
        for (int stride = size >> 1; stride >= 1024; stride >>= 1) {
            unsigned long long mine = sbuf[cur][t];
            unsigned long long other = dsmem_ld64(cur ? addr1 : addr0,
                                                  rank ^ (uint32_t)(stride >> 10));
            bool keepmin = (((ge & stride) == 0) == up);
            sbuf[cur ^ 1][t] = keepmin ? u64min(mine, other) : u64max(mine, other);
            CLUSTER_SYNC();
            cur ^= 1;
        }
        s = sbuf[cur];
        for (int stride = 512; stride >= 32; stride >>= 1) {
            if (t < 512) {
                int a = ((t & ~(stride - 1)) << 1) | (t & (stride - 1));
                int b = a + stride;
                unsigned long long xx = s[a], yy = s[b];
                if ((xx > yy) == up) { s[a] = yy; s[b] = xx; }
            }
            __syncthreads();
        }
        own = s[t];
        #pragma unroll
        for (int stride = 16; stride >= 1; stride >>= 1) {
            unsigned long long p = __shfl_xor_sync(0xFFFFFFFFu, own, stride);
            bool keepmin = (((t & stride) == 0) == up);
            own = keepmin ? u64min(own, p) : u64max(own, p);
        }
        s[t] = own;
        __syncthreads();
        CLUSTER_SYNC();
    }

    int idx = (int)(own & 0x1FFFu);
    uint32_t uu = (uint32_t)(own >> 13);
    uu ^= (uu & 0x80000000u) ? 0x80000000u : 0xFFFFFFFFu;
    g_key[ge] = __uint_as_float(uu);
    g_idx[ge] = idx;
}

// ==================== wspart: within-chunk partial scans + chunk sums ====================
__global__ void __launch_bounds__(288) wspart_kernel() {
    __shared__ float sh[CHL][OUTD];    // 16 KB
    __shared__ float sw1[CHL], sw2[CHL];
    const int c = blockIdx.x;
    const int k = threadIdx.x;

    if (k < CHL) {
        float m1 = g_key[N - 1];
        float d = g_key[c * CHL + k] - m1;
        sw1[k] = __expf(d);
        sw2[k] = __expf(LRELU_ALPHA * d);
    }
    for (int e = k; e < CHL * OUTD; e += 288) {
        int r = e >> 8, col = e & 255;
        sh[r][col] = g_h[(size_t)g_idx[c * CHL + r] * OUTD + col];
    }
    __syncthreads();

    if (k >= W257) return;

    float acc = 0.f;
    #pragma unroll 4
    for (int r = 0; r < CHL; ++r) {
        int p = c * CHL + r;
        g_P2[(size_t)p * W257 + k] = acc;
        float v = (k < OUTD) ? sh[r][k] : 1.0f;
        acc += sw2[r] * v;
    }
    g_cs2[k * NCH + c] = acc;
    if (c == NCH - 1) g_P2[(size_t)N * W257 + k] = acc;

    acc = 0.f;
    #pragma unroll 4
    for (int r = CHL - 1; r >= 0; --r) {
        int p = c * CHL + r;
        float v = (k < OUTD) ? sh[r][k] : 1.0f;
        acc += sw1[r] * v;
        g_SE[(size_t)p * W257 + k] = acc;
    }
    g_cs1[k * NCH + c] = acc;
    if (c == NCH - 1) g_SE[(size_t)N * W257 + k] = 0.f;
}

// ==================== chunkscan: exclusive offsets, transposed out ====================
__global__ void chunkscan_kernel() {
    int k = blockIdx.x;       // 0..256
    int t = threadIdx.x;      // 0..511
    int lane = t & 31, w = t >> 5;
    float a = g_cs2[k * NCH + t];
    float b = g_cs1[k * NCH + (NCH - 1 - t)];
    float ia = a, ib = b;
    #pragma unroll
    for (int o = 1; o < 32; o <<= 1) {
        float pa = __shfl_up_sync(0xFFFFFFFFu, ia, o);
        float pb = __shfl_up_sync(0xFFFFFFFFu, ib, o);
        if (lane >= o) { ia += pa; ib += pb; }
    }
    __shared__ float wa[16], wb[16];
    if (lane == 31) { wa[w] = ia; wb[w] = ib; }
    __syncthreads();
    if (t < 16) {
        float xa = wa[t], xb = wb[t];
        #pragma unroll
        for (int o = 1; o < 16; o <<= 1) {
            float pa = __shfl_up_sync(0xFFFFu, xa, o);
            float pb = __shfl_up_sync(0xFFFFu, xb, o);
            if (t >= o) { xa += pa; xb += pb; }
        }
        wa[t] = xa; wb[t] = xb;
    }
    __syncthreads();
    float offa = w ? wa[w - 1] : 0.f;
    float offb = w ? wb[w - 1] : 0.f;
    g_co2t[(size_t)t * W257 + k]             = ia - a + offa;   // exclusive prefix offset
    g_co1t[(size_t)(NCH - 1 - t) * W257 + k] = ib - b + offb;   // exclusive suffix offset
}

// ==================== epilogue: 32 rows per block, smem binary search ====================
__global__ void __launch_bounds__(256) out_kernel(float* __restrict__ out) {
    __shared__ float skey[N];          // 32 KB
    __shared__ int   sp[32];
    __shared__ float sr[32];
    const int tid = threadIdx.x;
    const int rb  = blockIdx.x * 32;

    #pragma unroll
    for (int i = 0; i < N / 4 / 256; ++i) {
        int e = (i * 256 + tid) * 4;
        *(float4*)&skey[e] = *(const float4*)&g_key[e];
    }
    __syncthreads();

    if (tid < 32) {
        int i = rb + tid;
        float m1 = skey[N - 1];
        float s2 = g_s2p[i] + g_s2p[N + i];
        float t = -s2;
        int lo = 0, hi = N;
        #pragma unroll
        for (int it = 0; it < 13; ++it) {
            int mid = (lo + hi) >> 1;
            if (skey[mid] > t) hi = mid; else lo = mid + 1;
        }
        sp[tid] = lo;
        sr[tid] = __expf((LRELU_ALPHA - 1.0f) * (s2 + m1));
    }
    __syncthreads();

    #pragma unroll 4
    for (int rr = 0; rr < 32; ++rr) {
        int p = sp[rr];
        int c = p >> 4;                 // CHL = 16
        if (c > NCH - 1) c = NCH - 1;   // p == N clamps to last chunk
        size_t basep = (size_t)p * W257;
        size_t basec = (size_t)c * W257;
        float r = sr[rr];
        float seN = g_SE[basep + OUTD] + g_co1t[basec + OUTD];
        float p2N = g_P2[basep + OUTD] + g_co2t[basec + OUTD];
        float den = seN + r * p2N;
        float se  = g_SE[basep + tid] + g_co1t[basec + tid];
        float p2  = g_P2[basep + tid] + g_co2t[basec + tid];
        out[(size_t)(rb + rr) * OUTD + tid] = (se + r * p2) / den;
    }
}

// ==================== launch: fork sort ∥ gemm, join before wspart ====================
extern "C" void kernel_launch(void* const* d_in, const int* in_sizes, int n_in,
                              void* d_out, int out_size) {
    const float* x  = (const float*)d_in[0];
    const float* Wm = (const float*)d_in[2];
    const float* a1 = (const float*)d_in[3];
    const float* a2 = (const float*)d_in[4];
    float* out = (float*)d_out;

    cudaStream_t side;
    cudaStreamCreateWithFlags(&side, cudaStreamNonBlocking);
    cudaEvent_t e0, e1;
    cudaEventCreateWithFlags(&e0, cudaEventDisableTiming);
    cudaEventCreateWithFlags(&e1, cudaEventDisableTiming);

    cudaEventRecord(e0, 0);                 // fork point on default stream
    cudaStreamWaitEvent(side, e0, 0);
    sort_kernel<<<8, 1024, 0, side>>>(x, Wm, a1);
    cudaEventRecord(e1, side);

    gemm_fused_kernel<<<dim3(2, 64), 256>>>(x, Wm, a2);   // default stream, concurrent

    cudaStreamWaitEvent(0, e1, 0);          // join
    wspart_kernel<<<NCH, 288>>>();
    chunkscan_kernel<<<W257, 512>>>();
    out_kernel<<<N / 32, 256>>>(out);

    cudaEventDestroy(e0);
    cudaEventDestroy(e1);
    cudaStreamDestroy(side);
}

// round 14
// speedup vs baseline: 1.5361x; 1.5361x over previous
#include <cuda_runtime.h>
#include <cuda_bf16.h>
#include <cstdint>

#define LRELU_ALPHA 0.2f

constexpr int N    = 8192;
constexpr int KIN  = 512;
constexpr int OUTD = 256;
constexpr int W257 = OUTD + 1;
constexpr int NCH  = 512;
constexpr int CHL  = N / NCH;    // 16

// ---------------- scratch (device globals; no allocation) ----------------
__device__ float g_h[N * OUTD];
__device__ float g_s1p[2 * N];
__device__ float g_s2p[2 * N];
__device__ float g_key[N];
__device__ int   g_idx[N];
__device__ float g_cs1[W257 * NCH];          // chunk sums [k][c]
__device__ float g_cs2[W257 * NCH];
__device__ float g_co1t[NCH * W257];         // exclusive suffix offsets, [c][k]
__device__ float g_co2t[NCH * W257];         // exclusive prefix offsets, [c][k]
__device__ float g_SE[(N + 1) * W257];       // within-chunk partial suffix
__device__ float g_P2[(N + 1) * W257];       // within-chunk partial prefix

__device__ __forceinline__ uint32_t smem_u32(const void* p) {
    uint32_t a;
    asm("{ .reg .u64 t; cvta.to.shared.u64 t, %1; cvt.u32.u64 %0, t; }" : "=r"(a) : "l"(p));
    return a;
}

// ==================== fused GEMM: h = x @ W^T, + s1/s2 partials ====================
constexpr int SSTR = 40;

__device__ __forceinline__ void ldsm_x4(uint32_t (&r)[4], uint32_t addr) {
    asm volatile("ldmatrix.sync.aligned.m8n8.x4.shared.b16 {%0,%1,%2,%3}, [%4];"
                 : "=r"(r[0]), "=r"(r[1]), "=r"(r[2]), "=r"(r[3]) : "r"(addr));
}
__device__ __forceinline__ void mma_bf16(float (&c)[4], const uint32_t (&a)[4],
                                         uint32_t b0, uint32_t b1) {
    asm volatile(
        "mma.sync.aligned.m16n8k16.row.col.f32.bf16.bf16.f32 "
        "{%0,%1,%2,%3}, {%4,%5,%6,%7}, {%8,%9}, {%0,%1,%2,%3};"
        : "+f"(c[0]), "+f"(c[1]), "+f"(c[2]), "+f"(c[3])
        : "r"(a[0]), "r"(a[1]), "r"(a[2]), "r"(a[3]), "r"(b0), "r"(b1));
}
__device__ __forceinline__ void cvt_hilo(float4 v, uint2& hi, uint2& lo) {
    __nv_bfloat16 h0 = __float2bfloat16(v.x), h1 = __float2bfloat16(v.y);
    __nv_bfloat16 h2 = __float2bfloat16(v.z), h3 = __float2bfloat16(v.w);
    __nv_bfloat16 l0 = __float2bfloat16(v.x - __bfloat162float(h0));
    __nv_bfloat16 l1 = __float2bfloat16(v.y - __bfloat162float(h1));
    __nv_bfloat16 l2 = __float2bfloat16(v.z - __bfloat162float(h2));
    __nv_bfloat16 l3 = __float2bfloat16(v.w - __bfloat162float(h3));
    __nv_bfloat162 p0(h0, h1), p1(h2, h3), q0(l0, l1), q1(l2, l3);
    hi.x = *reinterpret_cast<uint32_t*>(&p0);
    hi.y = *reinterpret_cast<uint32_t*>(&p1);
    lo.x = *reinterpret_cast<uint32_t*>(&q0);
    lo.y = *reinterpret_cast<uint32_t*>(&q1);
}

__global__ void __launch_bounds__(256, 1) gemm_fused_kernel(
    const float* __restrict__ x, const float* __restrict__ Wm,
    const float* __restrict__ a1, const float* __restrict__ a2) {
    __shared__ __nv_bfloat16 sAh[128 * SSTR];
    __shared__ __nv_bfloat16 sAl[128 * SSTR];
    __shared__ __nv_bfloat16 sBh[128 * SSTR];
    __shared__ __nv_bfloat16 sBl[128 * SSTR];

    const int tid  = threadIdx.x;
    const int wid  = tid >> 5;
    const int lane = tid & 31;
    const int wm   = wid & 1;
    const int wn   = wid >> 1;
    const int nb   = blockIdx.x;
    const int m0   = blockIdx.y * 128;
    const int n0   = nb * 128;

    const uint32_t bAh = smem_u32(sAh);
    const uint32_t bAl = smem_u32(sAl);
    const uint32_t bBh = smem_u32(sBh);
    const uint32_t bBl = smem_u32(sBl);

    int srow[4], scol[4];
    #pragma unroll
    for (int i = 0; i < 4; ++i) {
        int lin = i * 256 + tid;
        srow[i] = lin >> 3;
        scol[i] = (lin & 7) * 4;
    }

    float acc[4][4][4] = {};
    float4 pvx[4], pvw[4];

    #pragma unroll
    for (int i = 0; i < 4; ++i) {
        pvx[i] = *(const float4*)(x  + (size_t)(m0 + srow[i]) * KIN + scol[i]);
        pvw[i] = *(const float4*)(Wm + (size_t)(n0 + srow[i]) * KIN + scol[i]);
    }

    for (int kc = 0; kc < KIN / 32; ++kc) {
        #pragma unroll
        for (int i = 0; i < 4; ++i) {
            uint2 hi, lo;
            int so = srow[i] * SSTR + scol[i];
            cvt_hilo(pvx[i], hi, lo);
            *(uint2*)(sAh + so) = hi;
            *(uint2*)(sAl + so) = lo;
            cvt_hilo(pvw[i], hi, lo);
            *(uint2*)(sBh + so) = hi;
            *(uint2*)(sBl + so) = lo;
        }
        __syncthreads();

        if (kc + 1 < KIN / 32) {
            int kb = (kc + 1) * 32;
            #pragma unroll
            for (int i = 0; i < 4; ++i) {
                pvx[i] = *(const float4*)(x  + (size_t)(m0 + srow[i]) * KIN + kb + scol[i]);
                pvw[i] = *(const float4*)(Wm + (size_t)(n0 + srow[i]) * KIN + kb + scol[i]);
            }
        }

        #pragma unroll
        for (int kk = 0; kk < 2; ++kk) {
            uint32_t ah[4][4], al[4][4], bh[2][4], bl[2][4];
            #pragma unroll
            for (int mt = 0; mt < 4; ++mt) {
                uint32_t off = (uint32_t)((wm * 64 + mt * 16 + (lane & 15)) * SSTR
                                          + kk * 16 + (lane >> 4) * 8) * 2;
                ldsm_x4(ah[mt], bAh + off);
                ldsm_x4(al[mt], bAl + off);
            }
            #pragma unroll
            for (int ntp = 0; ntp < 2; ++ntp) {
                uint32_t off = (uint32_t)((wn * 32 + ntp * 16 + ((lane >> 4) * 8) + (lane & 7)) * SSTR
                                          + kk * 16 + ((lane >> 3) & 1) * 8) * 2;
                ldsm_x4(bh[ntp], bBh + off);
                ldsm_x4(bl[ntp], bBl + off);
            }
            #pragma unroll
            for (int mt = 0; mt < 4; ++mt)
                #pragma unroll
                for (int nf = 0; nf < 4; ++nf) {
                    uint32_t bh0 = bh[nf >> 1][(nf & 1) * 2], bh1 = bh[nf >> 1][(nf & 1) * 2 + 1];
                    uint32_t bl0 = bl[nf >> 1][(nf & 1) * 2], bl1 = bl[nf >> 1][(nf & 1) * 2 + 1];
                    mma_bf16(acc[mt][nf], ah[mt], bh0, bh1);
                    mma_bf16(acc[mt][nf], ah[mt], bl0, bl1);
                    mma_bf16(acc[mt][nf], al[mt], bh0, bh1);
                }
        }
        __syncthreads();
    }

    #pragma unroll
    for (int mt = 0; mt < 4; ++mt)
        #pragma unroll
        for (int nf = 0; nf < 4; ++nf) {
            int row0 = m0 + wm * 64 + mt * 16 + (lane >> 2);
            int col  = n0 + wn * 32 + nf * 8 + (lane & 3) * 2;
            *(float2*)&g_h[(size_t)row0 * OUTD + col] =
                make_float2(acc[mt][nf][0], acc[mt][nf][1]);
            *(float2*)&g_h[(size_t)(row0 + 8) * OUTD + col] =
                make_float2(acc[mt][nf][2], acc[mt][nf][3]);
        }

    float* red = (float*)sAh;
    #pragma unroll
    for (int mt = 0; mt < 4; ++mt) {
        float r1a = 0.f, r2a = 0.f, r1b = 0.f, r2b = 0.f;
        #pragma unroll
        for (int nf = 0; nf < 4; ++nf) {
            int col = n0 + wn * 32 + nf * 8 + (lane & 3) * 2;
            float a10 = a1[col], a11 = a1[col + 1];
            float a20 = a2[col], a21 = a2[col + 1];
            r1a += acc[mt][nf][0] * a10 + acc[mt][nf][1] * a11;
            r2a += acc[mt][nf][0] * a20 + acc[mt][nf][1] * a21;
            r1b += acc[mt][nf][2] * a10 + acc[mt][nf][3] * a11;
            r2b += acc[mt][nf][2] * a20 + acc[mt][nf][3] * a21;
        }
        #pragma unroll
        for (int o = 1; o <= 2; o <<= 1) {
            r1a += __shfl_xor_sync(0xFFFFFFFFu, r1a, o);
            r2a += __shfl_xor_sync(0xFFFFFFFFu, r2a, o);
            r1b += __shfl_xor_sync(0xFFFFFFFFu, r1b, o);
            r2b += __shfl_xor_sync(0xFFFFFFFFu, r2b, o);
        }
        if ((lane & 3) == 0) {
            int row = wm * 64 + mt * 16 + (lane >> 2);
            red[row * 4 + wn]             = r1a;
            red[512 + row * 4 + wn]       = r2a;
            red[(row + 8) * 4 + wn]       = r1b;
            red[512 + (row + 8) * 4 + wn] = r2b;
        }
    }
    __syncthreads();
    if (tid < 128) {
        float s1 = red[tid * 4] + red[tid * 4 + 1] + red[tid * 4 + 2] + red[tid * 4 + 3];
        float s2 = red[512 + tid * 4] + red[512 + tid * 4 + 1]
                 + red[512 + tid * 4 + 2] + red[512 + tid * 4 + 3];
        g_s1p[nb * N + m0 + tid] = s1;
        g_s2p[nb * N + m0 + tid] = s2;
    }
}

// ==================== 8-CTA cluster bitonic sort (double-buffered DSMEM) ====================
#define CLUSTER_SYNC() do {                                             \
    asm volatile("barrier.cluster.arrive.aligned;" ::: "memory");       \
    asm volatile("barrier.cluster.wait.aligned;" ::: "memory");         \
} while (0)

__device__ __forceinline__ unsigned long long dsmem_ld64(uint32_t laddr, uint32_t rank) {
    uint32_t ra;
    unsigned long long v;
    asm volatile("mapa.shared::cluster.u32 %0, %1, %2;" : "=r"(ra) : "r"(laddr), "r"(rank));
    asm volatile("ld.shared::cluster.u64 %0, [%1];" : "=l"(v) : "r"(ra) : "memory");
    return v;
}
__device__ __forceinline__ unsigned long long u64min(unsigned long long a, unsigned long long b) { return a < b ? a : b; }
__device__ __forceinline__ unsigned long long u64max(unsigned long long a, unsigned long long b) { return a < b ? b : a; }

__global__ void __launch_bounds__(1024, 1) __cluster_dims__(8, 1, 1) sort_kernel() {
    __shared__ unsigned long long sbuf[2][1024];
    const int t = threadIdx.x;
    uint32_t rank;
    asm("mov.u32 %0, %%cluster_ctarank;" : "=r"(rank));
    const int ge = (int)rank * 1024 + t;

    uint32_t u = __float_as_uint(g_s1p[ge] + g_s1p[N + ge]);
    u ^= (u & 0x80000000u) ? 0xFFFFFFFFu : 0x80000000u;
    unsigned long long own = ((unsigned long long)u << 13) | (unsigned)ge;

    // sizes 2..32: pure shuffles
    #pragma unroll
    for (int size = 2; size <= 32; size <<= 1) {
        bool up = ((ge & size) == 0);
        #pragma unroll
        for (int stride = size >> 1; stride >= 1; stride >>= 1) {
            unsigned long long p = __shfl_xor_sync(0xFFFFFFFFu, own, stride);
            bool keepmin = (((t & stride) == 0) == up);
            own = keepmin ? u64min(own, p) : u64max(own, p);
        }
    }
    int cur = 0;
    unsigned long long* s = sbuf[0];
    s[t] = own;
    __syncthreads();

    // sizes 64..1024: smem strides 32..512, shuffles below
    for (int size = 64; size <= 1024; size <<= 1) {
        for (int stride = size >> 1; stride >= 32; stride >>= 1) {
            if (t < 512) {
                int a = ((t & ~(stride - 1)) << 1) | (t & (stride - 1));
                int b = a + stride;
                bool up = ((((int)rank * 1024 + a) & size) == 0);
                unsigned long long x = s[a], y = s[b];
                if ((x > y) == up) { s[a] = y; s[b] = x; }
            }
            __syncthreads();
        }
        own = s[t];
        bool up = ((ge & size) == 0);
        #pragma unroll
        for (int stride = 16; stride >= 1; stride >>= 1) {
            unsigned long long p = __shfl_xor_sync(0xFFFFFFFFu, own, stride);
            bool keepmin = (((t & stride) == 0) == up);
            own = keepmin ? u64min(own, p) : u64max(own, p);
        }
        s[t] = own;
        __syncthreads();
    }

    CLUSTER_SYNC();   // all CTAs' buffer 0 valid

    const uint32_t addr0 = smem_u32(&sbuf[0][t]);
    const uint32_t addr1 = smem_u32(&sbuf[1][t]);
    for (int size = 2048; size <= 8192; size <<= 1) {
        bool up = ((ge & size) == 0);
        // cross-CTA stages: read cur (own + remote), write alt, single sync, flip
        for (int stride = size >> 1; stride >= 1024; stride >>= 1) {
            unsigned long long mine = sbuf[cur][t];
            unsigned long long other = dsmem_ld64(cur ? addr1 : addr0,
                                                  rank ^ (uint32_t)(stride >> 10));
            bool keepmin = (((ge & stride) == 0) == up);
            sbuf[cur ^ 1][t] = keepmin ? u64min(mine, other) : u64max(mine, other);
            CLUSTER_SYNC();
            cur ^= 1;
        }
        s = sbuf[cur];
        // within-CTA smem stages
        for (int stride = 512; stride >= 32; stride >>= 1) {
            if (t < 512) {
                int a = ((t & ~(stride - 1)) << 1) | (t & (stride - 1));
                int b = a + stride;
                unsigned long long x = s[a], y = s[b];
                if ((x > y) == up) { s[a] = y; s[b] = x; }
            }
            __syncthreads();
        }
        own = s[t];
        #pragma unroll
        for (int stride = 16; stride >= 1; stride >>= 1) {
            unsigned long long p = __shfl_xor_sync(0xFFFFFFFFu, own, stride);
            bool keepmin = (((t & stride) == 0) == up);
            own = keepmin ? u64min(own, p) : u64max(own, p);
        }
        s[t] = own;
        __syncthreads();
        CLUSTER_SYNC();   // cur buffer consistent cluster-wide before next size
    }

    int idx = (int)(own & 0x1FFFu);
    uint32_t uu = (uint32_t)(own >> 13);
    uu ^= (uu & 0x80000000u) ? 0x80000000u : 0xFFFFFFFFu;
    g_key[ge] = __uint_as_float(uu);
    g_idx[ge] = idx;
}

// ==================== wspart: within-chunk partial scans + chunk sums ====================
__global__ void __launch_bounds__(288) wspart_kernel() {
    __shared__ float sh[CHL][OUTD];    // 16 KB
    __shared__ float sw1[CHL], sw2[CHL];
    const int c = blockIdx.x;
    const int k = threadIdx.x;

    if (k < CHL) {
        float m1 = g_key[N - 1];
        float d = g_key[c * CHL + k] - m1;
        sw1[k] = __expf(d);
        sw2[k] = __expf(LRELU_ALPHA * d);
    }
    for (int e = k; e < CHL * OUTD; e += 288) {
        int r = e >> 8, col = e & 255;
        sh[r][col] = g_h[(size_t)g_idx[c * CHL + r] * OUTD + col];
    }
    __syncthreads();

    if (k >= W257) return;

    float acc = 0.f;
    #pragma unroll 4
    for (int r = 0; r < CHL; ++r) {
        int p = c * CHL + r;
        g_P2[(size_t)p * W257 + k] = acc;
        float v = (k < OUTD) ? sh[r][k] : 1.0f;
        acc += sw2[r] * v;
    }
    g_cs2[k * NCH + c] = acc;
    if (c == NCH - 1) g_P2[(size_t)N * W257 + k] = acc;

    acc = 0.f;
    #pragma unroll 4
    for (int r = CHL - 1; r >= 0; --r) {
        int p = c * CHL + r;
        float v = (k < OUTD) ? sh[r][k] : 1.0f;
        acc += sw1[r] * v;
        g_SE[(size_t)p * W257 + k] = acc;
    }
    g_cs1[k * NCH + c] = acc;
    if (c == NCH - 1) g_SE[(size_t)N * W257 + k] = 0.f;
}

// ==================== chunkscan: exclusive offsets, transposed out ====================
__global__ void chunkscan_kernel() {
    int k = blockIdx.x;       // 0..256
    int t = threadIdx.x;      // 0..511
    int lane = t & 31, w = t >> 5;
    float a = g_cs2[k * NCH + t];
    float b = g_cs1[k * NCH + (NCH - 1 - t)];
    float ia = a, ib = b;
    #pragma unroll
    for (int o = 1; o < 32; o <<= 1) {
        float pa = __shfl_up_sync(0xFFFFFFFFu, ia, o);
        float pb = __shfl_up_sync(0xFFFFFFFFu, ib, o);
        if (lane >= o) { ia += pa; ib += pb; }
    }
    __shared__ float wa[16], wb[16];
    if (lane == 31) { wa[w] = ia; wb[w] = ib; }
    __syncthreads();
    if (t < 16) {
        float xa = wa[t], xb = wb[t];
        #pragma unroll
        for (int o = 1; o < 16; o <<= 1) {
            float pa = __shfl_up_sync(0xFFFFu, xa, o);
            float pb = __shfl_up_sync(0xFFFFu, xb, o);
            if (t >= o) { xa += pa; xb += pb; }
        }
        wa[t] = xa; wb[t] = xb;
    }
    __syncthreads();
    float offa = w ? wa[w - 1] : 0.f;
    float offb = w ? wb[w - 1] : 0.f;
    g_co2t[(size_t)t * W257 + k]             = ia - a + offa;   // exclusive prefix offset
    g_co1t[(size_t)(NCH - 1 - t) * W257 + k] = ib - b + offb;   // exclusive suffix offset
}

// ==================== epilogue: 64 rows per block, smem binary search ====================
__global__ void __launch_bounds__(256) out_kernel(float* __restrict__ out) {
    __shared__ float skey[N];          // 32 KB
    __shared__ int   sp[64];
    __shared__ float sr[64];
    const int tid = threadIdx.x;
    const int rb  = blockIdx.x * 64;

    #pragma unroll
    for (int i = 0; i < N / 4 / 256; ++i) {
        int e = (i * 256 + tid) * 4;
        *(float4*)&skey[e] = *(const float4*)&g_key[e];
    }
    __syncthreads();

    if (tid < 64) {
        int i = rb + tid;
        float m1 = skey[N - 1];
        float s2 = g_s2p[i] + g_s2p[N + i];
        float t = -s2;
        int lo = 0, hi = N;
        #pragma unroll
        for (int it = 0; it < 13; ++it) {
            int mid = (lo + hi) >> 1;
            if (skey[mid] > t) hi = mid; else lo = mid + 1;
        }
        sp[tid] = lo;
        sr[tid] = __expf((LRELU_ALPHA - 1.0f) * (s2 + m1));
    }
    __syncthreads();

    #pragma unroll 4
    for (int rr = 0; rr < 64; ++rr) {
        int p = sp[rr];
        int c = p >> 4;                 // CHL = 16
        if (c > NCH - 1) c = NCH - 1;   // p == N clamps to last chunk
        size_t basep = (size_t)p * W257;
        size_t basec = (size_t)c * W257;
        float r = sr[rr];
        float seN = g_SE[basep + OUTD] + g_co1t[basec + OUTD];
        float p2N = g_P2[basep + OUTD] + g_co2t[basec + OUTD];
        float den = seN + r * p2N;
        float se  = g_SE[basep + tid] + g_co1t[basec + tid];
        float p2  = g_P2[basep + tid] + g_co2t[basec + tid];
        out[(size_t)(rb + rr) * OUTD + tid] = (se + r * p2) / den;
    }
}

// ==================== launch ====================
extern "C" void kernel_launch(void* const* d_in, const int* in_sizes, int n_in,
                              void* d_out, int out_size) {
    const float* x  = (const float*)d_in[0];
    const float* Wm = (const float*)d_in[2];
    const float* a1 = (const float*)d_in[3];
    const float* a2 = (const float*)d_in[4];
    float* out = (float*)d_out;

    gemm_fused_kernel<<<dim3(2, 64), 256>>>(x, Wm, a1, a2);
    sort_kernel<<<8, 1024>>>();
    wspart_kernel<<<NCH, 288>>>();
    chunkscan_kernel<<<W257, 512>>>();
    out_kernel<<<N / 64, 256>>>(out);
}

// round 15
// speedup vs baseline: 1.8128x; 1.1801x over previous
#include <cuda_runtime.h>
#include <cuda_bf16.h>
#include <cstdint>

#define LRELU_ALPHA 0.2f

constexpr int N    = 8192;
constexpr int KIN  = 512;
constexpr int OUTD = 256;
constexpr int W257 = OUTD + 1;
constexpr int NCH  = 512;
constexpr int CHL  = N / NCH;    // 16

// ---------------- scratch (device globals; no allocation) ----------------
__device__ float g_h[N * OUTD];
__device__ float g_s1p[2 * N];
__device__ float g_s2p[2 * N];
__device__ float g_key[N];
__device__ int   g_idx[N];
__device__ float g_cs1[W257 * NCH];          // chunk sums [k][c]
__device__ float g_cs2[W257 * NCH];
__device__ float g_co1t[NCH * W257];         // exclusive suffix offsets, [c][k]
__device__ float g_co2t[NCH * W257];         // exclusive prefix offsets, [c][k]
__device__ float g_SE[(N + 1) * W257];       // within-chunk partial suffix
__device__ float g_P2[(N + 1) * W257];       // within-chunk partial prefix

__device__ __forceinline__ uint32_t smem_u32(const void* p) {
    uint32_t a;
    asm("{ .reg .u64 t; cvta.to.shared.u64 t, %1; cvt.u32.u64 %0, t; }" : "=r"(a) : "l"(p));
    return a;
}

// ==================== fused GEMM: h = x @ W^T, + s1/s2 partials ====================
constexpr int SSTR = 40;

__device__ __forceinline__ void ldsm_x4(uint32_t (&r)[4], uint32_t addr) {
    asm volatile("ldmatrix.sync.aligned.m8n8.x4.shared.b16 {%0,%1,%2,%3}, [%4];"
                 : "=r"(r[0]), "=r"(r[1]), "=r"(r[2]), "=r"(r[3]) : "r"(addr));
}
__device__ __forceinline__ void mma_bf16(float (&c)[4], const uint32_t (&a)[4],
                                         uint32_t b0, uint32_t b1) {
    asm volatile(
        "mma.sync.aligned.m16n8k16.row.col.f32.bf16.bf16.f32 "
        "{%0,%1,%2,%3}, {%4,%5,%6,%7}, {%8,%9}, {%0,%1,%2,%3};"
        : "+f"(c[0]), "+f"(c[1]), "+f"(c[2]), "+f"(c[3])
        : "r"(a[0]), "r"(a[1]), "r"(a[2]), "r"(a[3]), "r"(b0), "r"(b1));
}
__device__ __forceinline__ void cvt_hilo(float4 v, uint2& hi, uint2& lo) {
    __nv_bfloat16 h0 = __float2bfloat16(v.x), h1 = __float2bfloat16(v.y);
    __nv_bfloat16 h2 = __float2bfloat16(v.z), h3 = __float2bfloat16(v.w);
    __nv_bfloat16 l0 = __float2bfloat16(v.x - __bfloat162float(h0));
    __nv_bfloat16 l1 = __float2bfloat16(v.y - __bfloat162float(h1));
    __nv_bfloat16 l2 = __float2bfloat16(v.z - __bfloat162float(h2));
    __nv_bfloat16 l3 = __float2bfloat16(v.w - __bfloat162float(h3));
    __nv_bfloat162 p0(h0, h1), p1(h2, h3), q0(l0, l1), q1(l2, l3);
    hi.x = *reinterpret_cast<uint32_t*>(&p0);
    hi.y = *reinterpret_cast<uint32_t*>(&p1);
    lo.x = *reinterpret_cast<uint32_t*>(&q0);
    lo.y = *reinterpret_cast<uint32_t*>(&q1);
}

__global__ void __launch_bounds__(256, 1) gemm_fused_kernel(
    const float* __restrict__ x, const float* __restrict__ Wm,
    const float* __restrict__ a1, const float* __restrict__ a2) {
    __shared__ __nv_bfloat16 sAh[128 * SSTR];
    __shared__ __nv_bfloat16 sAl[128 * SSTR];
    __shared__ __nv_bfloat16 sBh[128 * SSTR];
    __shared__ __nv_bfloat16 sBl[128 * SSTR];

    const int tid  = threadIdx.x;
    const int wid  = tid >> 5;
    const int lane = tid & 31;
    const int wm   = wid & 1;
    const int wn   = wid >> 1;
    const int nb   = blockIdx.x;
    const int m0   = blockIdx.y * 128;
    const int n0   = nb * 128;

    const uint32_t bAh = smem_u32(sAh);
    const uint32_t bAl = smem_u32(sAl);
    const uint32_t bBh = smem_u32(sBh);
    const uint32_t bBl = smem_u32(sBl);

    int srow[4], scol[4];
    #pragma unroll
    for (int i = 0; i < 4; ++i) {
        int lin = i * 256 + tid;
        srow[i] = lin >> 3;
        scol[i] = (lin & 7) * 4;
    }

    float acc[4][4][4] = {};
    float4 pvx[4], pvw[4];

    #pragma unroll
    for (int i = 0; i < 4; ++i) {
        pvx[i] = *(const float4*)(x  + (size_t)(m0 + srow[i]) * KIN + scol[i]);
        pvw[i] = *(const float4*)(Wm + (size_t)(n0 + srow[i]) * KIN + scol[i]);
    }

    for (int kc = 0; kc < KIN / 32; ++kc) {
        #pragma unroll
        for (int i = 0; i < 4; ++i) {
            uint2 hi, lo;
            int so = srow[i] * SSTR + scol[i];
            cvt_hilo(pvx[i], hi, lo);
            *(uint2*)(sAh + so) = hi;
            *(uint2*)(sAl + so) = lo;
            cvt_hilo(pvw[i], hi, lo);
            *(uint2*)(sBh + so) = hi;
            *(uint2*)(sBl + so) = lo;
        }
        __syncthreads();

        if (kc + 1 < KIN / 32) {
            int kb = (kc + 1) * 32;
            #pragma unroll
            for (int i = 0; i < 4; ++i) {
                pvx[i] = *(const float4*)(x  + (size_t)(m0 + srow[i]) * KIN + kb + scol[i]);
                pvw[i] = *(const float4*)(Wm + (size_t)(n0 + srow[i]) * KIN + kb + scol[i]);
            }
        }

        #pragma unroll
        for (int kk = 0; kk < 2; ++kk) {
            uint32_t ah[4][4], al[4][4], bh[2][4], bl[2][4];
            #pragma unroll
            for (int mt = 0; mt < 4; ++mt) {
                uint32_t off = (uint32_t)((wm * 64 + mt * 16 + (lane & 15)) * SSTR
                                          + kk * 16 + (lane >> 4) * 8) * 2;
                ldsm_x4(ah[mt], bAh + off);
                ldsm_x4(al[mt], bAl + off);
            }
            #pragma unroll
            for (int ntp = 0; ntp < 2; ++ntp) {
                uint32_t off = (uint32_t)((wn * 32 + ntp * 16 + ((lane >> 4) * 8) + (lane & 7)) * SSTR
                                          + kk * 16 + ((lane >> 3) & 1) * 8) * 2;
                ldsm_x4(bh[ntp], bBh + off);
                ldsm_x4(bl[ntp], bBl + off);
            }
            #pragma unroll
            for (int mt = 0; mt < 4; ++mt)
                #pragma unroll
                for (int nf = 0; nf < 4; ++nf) {
                    uint32_t bh0 = bh[nf >> 1][(nf & 1) * 2], bh1 = bh[nf >> 1][(nf & 1) * 2 + 1];
                    uint32_t bl0 = bl[nf >> 1][(nf & 1) * 2], bl1 = bl[nf >> 1][(nf & 1) * 2 + 1];
                    mma_bf16(acc[mt][nf], ah[mt], bh0, bh1);
                    mma_bf16(acc[mt][nf], ah[mt], bl0, bl1);
                    mma_bf16(acc[mt][nf], al[mt], bh0, bh1);
                }
        }
        __syncthreads();
    }

    #pragma unroll
    for (int mt = 0; mt < 4; ++mt)
        #pragma unroll
        for (int nf = 0; nf < 4; ++nf) {
            int row0 = m0 + wm * 64 + mt * 16 + (lane >> 2);
            int col  = n0 + wn * 32 + nf * 8 + (lane & 3) * 2;
            *(float2*)&g_h[(size_t)row0 * OUTD + col] =
                make_float2(acc[mt][nf][0], acc[mt][nf][1]);
            *(float2*)&g_h[(size_t)(row0 + 8) * OUTD + col] =
                make_float2(acc[mt][nf][2], acc[mt][nf][3]);
        }

    float* red = (float*)sAh;
    #pragma unroll
    for (int mt = 0; mt < 4; ++mt) {
        float r1a = 0.f, r2a = 0.f, r1b = 0.f, r2b = 0.f;
        #pragma unroll
        for (int nf = 0; nf < 4; ++nf) {
            int col = n0 + wn * 32 + nf * 8 + (lane & 3) * 2;
            float a10 = a1[col], a11 = a1[col + 1];
            float a20 = a2[col], a21 = a2[col + 1];
            r1a += acc[mt][nf][0] * a10 + acc[mt][nf][1] * a11;
            r2a += acc[mt][nf][0] * a20 + acc[mt][nf][1] * a21;
            r1b += acc[mt][nf][2] * a10 + acc[mt][nf][3] * a11;
            r2b += acc[mt][nf][2] * a20 + acc[mt][nf][3] * a21;
        }
        #pragma unroll
        for (int o = 1; o <= 2; o <<= 1) {
            r1a += __shfl_xor_sync(0xFFFFFFFFu, r1a, o);
            r2a += __shfl_xor_sync(0xFFFFFFFFu, r2a, o);
            r1b += __shfl_xor_sync(0xFFFFFFFFu, r1b, o);
            r2b += __shfl_xor_sync(0xFFFFFFFFu, r2b, o);
        }
        if ((lane & 3) == 0) {
            int row = wm * 64 + mt * 16 + (lane >> 2);
            red[row * 4 + wn]             = r1a;
            red[512 + row * 4 + wn]       = r2a;
            red[(row + 8) * 4 + wn]       = r1b;
            red[512 + (row + 8) * 4 + wn] = r2b;
        }
    }
    __syncthreads();
    if (tid < 128) {
        float s1 = red[tid * 4] + red[tid * 4 + 1] + red[tid * 4 + 2] + red[tid * 4 + 3];
        float s2 = red[512 + tid * 4] + red[512 + tid * 4 + 1]
                 + red[512 + tid * 4 + 2] + red[512 + tid * 4 + 3];
        g_s1p[nb * N + m0 + tid] = s1;
        g_s2p[nb * N + m0 + tid] = s2;
    }
}

// ==================== 8-CTA cluster bitonic sort (double-buffered DSMEM) ====================
#define CLUSTER_SYNC() do {                                             \
    asm volatile("barrier.cluster.arrive.aligned;" ::: "memory");       \
    asm volatile("barrier.cluster.wait.aligned;" ::: "memory");         \
} while (0)

__device__ __forceinline__ unsigned long long dsmem_ld64(uint32_t laddr, uint32_t rank) {
    uint32_t ra;
    unsigned long long v;
    asm volatile("mapa.shared::cluster.u32 %0, %1, %2;" : "=r"(ra) : "r"(laddr), "r"(rank));
    asm volatile("ld.shared::cluster.u64 %0, [%1];" : "=l"(v) : "r"(ra) : "memory");
    return v;
}
__device__ __forceinline__ unsigned long long u64min(unsigned long long a, unsigned long long b) { return a < b ? a : b; }
__device__ __forceinline__ unsigned long long u64max(unsigned long long a, unsigned long long b) { return a < b ? b : a; }

__global__ void __launch_bounds__(1024, 1) __cluster_dims__(8, 1, 1) sort_kernel() {
    __shared__ unsigned long long sbuf[2][1024];
    const int t = threadIdx.x;
    uint32_t rank;
    asm("mov.u32 %0, %%cluster_ctarank;" : "=r"(rank));
    const int ge = (int)rank * 1024 + t;

    uint32_t u = __float_as_uint(g_s1p[ge] + g_s1p[N + ge]);
    u ^= (u & 0x80000000u) ? 0xFFFFFFFFu : 0x80000000u;
    unsigned long long own = ((unsigned long long)u << 13) | (unsigned)ge;

    // sizes 2..32: pure shuffles
    #pragma unroll
    for (int size = 2; size <= 32; size <<= 1) {
        bool up = ((ge & size) == 0);
        #pragma unroll
        for (int stride = size >> 1; stride >= 1; stride >>= 1) {
            unsigned long long p = __shfl_xor_sync(0xFFFFFFFFu, own, stride);
            bool keepmin = (((t & stride) == 0) == up);
            own = keepmin ? u64min(own, p) : u64max(own, p);
        }
    }
    int cur = 0;
    unsigned long long* s = sbuf[0];
    s[t] = own;
    __syncthreads();

    // sizes 64..1024: smem strides 32..512, shuffles below
    for (int size = 64; size <= 1024; size <<= 1) {
        for (int stride = size >> 1; stride >= 32; stride >>= 1) {
            if (t < 512) {
                int a = ((t & ~(stride - 1)) << 1) | (t & (stride - 1));
                int b = a + stride;
                bool up = ((((int)rank * 1024 + a) & size) == 0);
                unsigned long long x = s[a], y = s[b];
                if ((x > y) == up) { s[a] = y; s[b] = x; }
            }
            __syncthreads();
        }
        own = s[t];
        bool up = ((ge & size) == 0);
        #pragma unroll
        for (int stride = 16; stride >= 1; stride >>= 1) {
            unsigned long long p = __shfl_xor_sync(0xFFFFFFFFu, own, stride);
            bool keepmin = (((t & stride) == 0) == up);
            own = keepmin ? u64min(own, p) : u64max(own, p);
        }
        s[t] = own;
        __syncthreads();
    }

    CLUSTER_SYNC();   // all CTAs' buffer 0 valid

    const uint32_t addr0 = smem_u32(&sbuf[0][t]);
    const uint32_t addr1 = smem_u32(&sbuf[1][t]);
    for (int size = 2048; size <= 8192; size <<= 1) {
        bool up = ((ge & size) == 0);
        // cross-CTA stages: read cur (own + remote), write alt, single sync, flip
        for (int stride = size >> 1; stride >= 1024; stride >>= 1) {
            unsigned long long mine = sbuf[cur][t];
            unsigned long long other = dsmem_ld64(cur ? addr1 : addr0,
                                                  rank ^ (uint32_t)(stride >> 10));
            bool keepmin = (((ge & stride) == 0) == up);
            sbuf[cur ^ 1][t] = keepmin ? u64min(mine, other) : u64max(mine, other);
            CLUSTER_SYNC();
            cur ^= 1;
        }
        s = sbuf[cur];
        // within-CTA smem stages
        for (int stride = 512; stride >= 32; stride >>= 1) {
            if (t < 512) {
                int a = ((t & ~(stride - 1)) << 1) | (t & (stride - 1));
                int b = a + stride;
                unsigned long long x = s[a], y = s[b];
                if ((x > y) == up) { s[a] = y; s[b] = x; }
            }
            __syncthreads();
        }
        own = s[t];
        #pragma unroll
        for (int stride = 16; stride >= 1; stride >>= 1) {
            unsigned long long p = __shfl_xor_sync(0xFFFFFFFFu, own, stride);
            bool keepmin = (((t & stride) == 0) == up);
            own = keepmin ? u64min(own, p) : u64max(own, p);
        }
        s[t] = own;
        __syncthreads();
        CLUSTER_SYNC();   // cur buffer consistent cluster-wide before next size
    }

    int idx = (int)(own & 0x1FFFu);
    uint32_t uu = (uint32_t)(own >> 13);
    uu ^= (uu & 0x80000000u) ? 0x80000000u : 0xFFFFFFFFu;
    g_key[ge] = __uint_as_float(uu);
    g_idx[ge] = idx;
}

// ==================== wspart: within-chunk partial scans + chunk sums ====================
__global__ void __launch_bounds__(288) wspart_kernel() {
    __shared__ float sh[CHL][OUTD];    // 16 KB
    __shared__ float sw1[CHL], sw2[CHL];
    const int c = blockIdx.x;
    const int k = threadIdx.x;

    if (k < CHL) {
        float m1 = g_key[N - 1];
        float d = g_key[c * CHL + k] - m1;
        sw1[k] = __expf(d);
        sw2[k] = __expf(LRELU_ALPHA * d);
    }
    for (int e = k; e < CHL * OUTD; e += 288) {
        int r = e >> 8, col = e & 255;
        sh[r][col] = g_h[(size_t)g_idx[c * CHL + r] * OUTD + col];
    }
    __syncthreads();

    if (k >= W257) return;

    float acc = 0.f;
    #pragma unroll 4
    for (int r = 0; r < CHL; ++r) {
        int p = c * CHL + r;
        g_P2[(size_t)p * W257 + k] = acc;
        float v = (k < OUTD) ? sh[r][k] : 1.0f;
        acc += sw2[r] * v;
    }
    g_cs2[k * NCH + c] = acc;
    if (c == NCH - 1) g_P2[(size_t)N * W257 + k] = acc;

    acc = 0.f;
    #pragma unroll 4
    for (int r = CHL - 1; r >= 0; --r) {
        int p = c * CHL + r;
        float v = (k < OUTD) ? sh[r][k] : 1.0f;
        acc += sw1[r] * v;
        g_SE[(size_t)p * W257 + k] = acc;
    }
    g_cs1[k * NCH + c] = acc;
    if (c == NCH - 1) g_SE[(size_t)N * W257 + k] = 0.f;
}

// ==================== chunkscan: exclusive offsets, transposed out ====================
__global__ void chunkscan_kernel() {
    int k = blockIdx.x;       // 0..256
    int t = threadIdx.x;      // 0..511
    int lane = t & 31, w = t >> 5;
    float a = g_cs2[k * NCH + t];
    float b = g_cs1[k * NCH + (NCH - 1 - t)];
    float ia = a, ib = b;
    #pragma unroll
    for (int o = 1; o < 32; o <<= 1) {
        float pa = __shfl_up_sync(0xFFFFFFFFu, ia, o);
        float pb = __shfl_up_sync(0xFFFFFFFFu, ib, o);
        if (lane >= o) { ia += pa; ib += pb; }
    }
    __shared__ float wa[16], wb[16];
    if (lane == 31) { wa[w] = ia; wb[w] = ib; }
    __syncthreads();
    if (t < 16) {
        float xa = wa[t], xb = wb[t];
        #pragma unroll
        for (int o = 1; o < 16; o <<= 1) {
            float pa = __shfl_up_sync(0xFFFFu, xa, o);
            float pb = __shfl_up_sync(0xFFFFu, xb, o);
            if (t >= o) { xa += pa; xb += pb; }
        }
        wa[t] = xa; wb[t] = xb;
    }
    __syncthreads();
    float offa = w ? wa[w - 1] : 0.f;
    float offb = w ? wb[w - 1] : 0.f;
    g_co2t[(size_t)t * W257 + k]             = ia - a + offa;   // exclusive prefix offset
    g_co1t[(size_t)(NCH - 1 - t) * W257 + k] = ib - b + offb;   // exclusive suffix offset
}

// ==================== epilogue: 32 rows per block, smem binary search ====================
__global__ void __launch_bounds__(256) out_kernel(float* __restrict__ out) {
    __shared__ float skey[N];          // 32 KB
    __shared__ int   sp[32];
    __shared__ float sr[32];
    const int tid = threadIdx.x;
    const int rb  = blockIdx.x * 32;

    #pragma unroll
    for (int i = 0; i < N / 4 / 256; ++i) {
        int e = (i * 256 + tid) * 4;
        *(float4*)&skey[e] = *(const float4*)&g_key[e];
    }
    __syncthreads();

    if (tid < 32) {
        int i = rb + tid;
        float m1 = skey[N - 1];
        float s2 = g_s2p[i] + g_s2p[N + i];
        float t = -s2;
        int lo = 0, hi = N;
        #pragma unroll
        for (int it = 0; it < 13; ++it) {
            int mid = (lo + hi) >> 1;
            if (skey[mid] > t) hi = mid; else lo = mid + 1;
        }
        sp[tid] = lo;
        sr[tid] = __expf((LRELU_ALPHA - 1.0f) * (s2 + m1));
    }
    __syncthreads();

    #pragma unroll 4
    for (int rr = 0; rr < 32; ++rr) {
        int p = sp[rr];
        int c = p >> 4;                 // CHL = 16
        if (c > NCH - 1) c = NCH - 1;   // p == N clamps to last chunk
        size_t basep = (size_t)p * W257;
        size_t basec = (size_t)c * W257;
        float r = sr[rr];
        float seN = g_SE[basep + OUTD] + g_co1t[basec + OUTD];
        float p2N = g_P2[basep + OUTD] + g_co2t[basec + OUTD];
        float den = seN + r * p2N;
        float se  = g_SE[basep + tid] + g_co1t[basec + tid];
        float p2  = g_P2[basep + tid] + g_co2t[basec + tid];
        out[(size_t)(rb + rr) * OUTD + tid] = (se + r * p2) / den;
    }
}

// ==================== launch ====================
extern "C" void kernel_launch(void* const* d_in, const int* in_sizes, int n_in,
                              void* d_out, int out_size) {
    const float* x  = (const float*)d_in[0];
    const float* Wm = (const float*)d_in[2];
    const float* a1 = (const float*)d_in[3];
    const float* a2 = (const float*)d_in[4];
    float* out = (float*)d_out;

    gemm_fused_kernel<<<dim3(2, 64), 256>>>(x, Wm, a1, a2);
    sort_kernel<<<8, 1024>>>();
    wspart_kernel<<<NCH, 288>>>();
    chunkscan_kernel<<<W257, 512>>>();
    out_kernel<<<N / 32, 256>>>(out);
}

// round 16
// speedup vs baseline: 1.8669x; 1.0298x over previous
#include <cuda_runtime.h>
#include <cuda_bf16.h>
#include <cstdint>

#define LRELU_ALPHA 0.2f

constexpr int N    = 8192;
constexpr int KIN  = 512;
constexpr int OUTD = 256;
constexpr int W257 = OUTD + 1;
constexpr int NCH  = 512;
constexpr int CHL  = N / NCH;    // 16

// ---------------- scratch (device globals; no allocation) ----------------
__device__ float g_h[N * OUTD];
__device__ float g_s1p[2 * N];
__device__ float g_s2p[2 * N];
__device__ float g_key[N];
__device__ int   g_idx[N];
__device__ float g_cs1[W257 * NCH];          // chunk sums [k][c]
__device__ float g_cs2[W257 * NCH];
__device__ float g_co1t[NCH * W257];         // exclusive suffix offsets, [c][k]
__device__ float g_co2t[NCH * W257];         // exclusive prefix offsets, [c][k]
__device__ float g_SE[(N + 1) * W257];       // within-chunk partial suffix
__device__ float g_P2[(N + 1) * W257];       // within-chunk partial prefix

__device__ __forceinline__ uint32_t smem_u32(const void* p) {
    uint32_t a;
    asm("{ .reg .u64 t; cvta.to.shared.u64 t, %1; cvt.u32.u64 %0, t; }" : "=r"(a) : "l"(p));
    return a;
}

// ==================== fused GEMM: h = x @ W^T, + s1/s2 partials ====================
constexpr int SSTR = 40;

__device__ __forceinline__ void ldsm_x4(uint32_t (&r)[4], uint32_t addr) {
    asm volatile("ldmatrix.sync.aligned.m8n8.x4.shared.b16 {%0,%1,%2,%3}, [%4];"
                 : "=r"(r[0]), "=r"(r[1]), "=r"(r[2]), "=r"(r[3]) : "r"(addr));
}
__device__ __forceinline__ void mma_bf16(float (&c)[4], const uint32_t (&a)[4],
                                         uint32_t b0, uint32_t b1) {
    asm volatile(
        "mma.sync.aligned.m16n8k16.row.col.f32.bf16.bf16.f32 "
        "{%0,%1,%2,%3}, {%4,%5,%6,%7}, {%8,%9}, {%0,%1,%2,%3};"
        : "+f"(c[0]), "+f"(c[1]), "+f"(c[2]), "+f"(c[3])
        : "r"(a[0]), "r"(a[1]), "r"(a[2]), "r"(a[3]), "r"(b0), "r"(b1));
}
__device__ __forceinline__ void cvt_hilo(float4 v, uint2& hi, uint2& lo) {
    __nv_bfloat16 h0 = __float2bfloat16(v.x), h1 = __float2bfloat16(v.y);
    __nv_bfloat16 h2 = __float2bfloat16(v.z), h3 = __float2bfloat16(v.w);
    __nv_bfloat16 l0 = __float2bfloat16(v.x - __bfloat162float(h0));
    __nv_bfloat16 l1 = __float2bfloat16(v.y - __bfloat162float(h1));
    __nv_bfloat16 l2 = __float2bfloat16(v.z - __bfloat162float(h2));
    __nv_bfloat16 l3 = __float2bfloat16(v.w - __bfloat162float(h3));
    __nv_bfloat162 p0(h0, h1), p1(h2, h3), q0(l0, l1), q1(l2, l3);
    hi.x = *reinterpret_cast<uint32_t*>(&p0);
    hi.y = *reinterpret_cast<uint32_t*>(&p1);
    lo.x = *reinterpret_cast<uint32_t*>(&q0);
    lo.y = *reinterpret_cast<uint32_t*>(&q1);
}

__global__ void __launch_bounds__(256, 1) gemm_fused_kernel(
    const float* __restrict__ x, const float* __restrict__ Wm,
    const float* __restrict__ a1, const float* __restrict__ a2) {
    __shared__ __nv_bfloat16 sAh[128 * SSTR];
    __shared__ __nv_bfloat16 sAl[128 * SSTR];
    __shared__ __nv_bfloat16 sBh[128 * SSTR];
    __shared__ __nv_bfloat16 sBl[128 * SSTR];

    const int tid  = threadIdx.x;
    const int wid  = tid >> 5;
    const int lane = tid & 31;
    const int wm   = wid & 1;
    const int wn   = wid >> 1;
    const int nb   = blockIdx.x;
    const int m0   = blockIdx.y * 128;
    const int n0   = nb * 128;

    const uint32_t bAh = smem_u32(sAh);
    const uint32_t bAl = smem_u32(sAl);
    const uint32_t bBh = smem_u32(sBh);
    const uint32_t bBl = smem_u32(sBl);

    int srow[4], scol[4];
    #pragma unroll
    for (int i = 0; i < 4; ++i) {
        int lin = i * 256 + tid;
        srow[i] = lin >> 3;
        scol[i] = (lin & 7) * 4;
    }

    float acc[4][4][4] = {};
    float4 pvx[4], pvw[4];

    #pragma unroll
    for (int i = 0; i < 4; ++i) {
        pvx[i] = *(const float4*)(x  + (size_t)(m0 + srow[i]) * KIN + scol[i]);
        pvw[i] = *(const float4*)(Wm + (size_t)(n0 + srow[i]) * KIN + scol[i]);
    }

    for (int kc = 0; kc < KIN / 32; ++kc) {
        #pragma unroll
        for (int i = 0; i < 4; ++i) {
            uint2 hi, lo;
            int so = srow[i] * SSTR + scol[i];
            cvt_hilo(pvx[i], hi, lo);
            *(uint2*)(sAh + so) = hi;
            *(uint2*)(sAl + so) = lo;
            cvt_hilo(pvw[i], hi, lo);
            *(uint2*)(sBh + so) = hi;
            *(uint2*)(sBl + so) = lo;
        }
        __syncthreads();

        if (kc + 1 < KIN / 32) {
            int kb = (kc + 1) * 32;
            #pragma unroll
            for (int i = 0; i < 4; ++i) {
                pvx[i] = *(const float4*)(x  + (size_t)(m0 + srow[i]) * KIN + kb + scol[i]);
                pvw[i] = *(const float4*)(Wm + (size_t)(n0 + srow[i]) * KIN + kb + scol[i]);
            }
        }

        #pragma unroll
        for (int kk = 0; kk < 2; ++kk) {
            uint32_t ah[4][4], al[4][4], bh[2][4], bl[2][4];
            #pragma unroll
            for (int mt = 0; mt < 4; ++mt) {
                uint32_t off = (uint32_t)((wm * 64 + mt * 16 + (lane & 15)) * SSTR
                                          + kk * 16 + (lane >> 4) * 8) * 2;
                ldsm_x4(ah[mt], bAh + off);
                ldsm_x4(al[mt], bAl + off);
            }
            #pragma unroll
            for (int ntp = 0; ntp < 2; ++ntp) {
                uint32_t off = (uint32_t)((wn * 32 + ntp * 16 + ((lane >> 4) * 8) + (lane & 7)) * SSTR
                                          + kk * 16 + ((lane >> 3) & 1) * 8) * 2;
                ldsm_x4(bh[ntp], bBh + off);
                ldsm_x4(bl[ntp], bBl + off);
            }
            #pragma unroll
            for (int mt = 0; mt < 4; ++mt)
                #pragma unroll
                for (int nf = 0; nf < 4; ++nf) {
                    uint32_t bh0 = bh[nf >> 1][(nf & 1) * 2], bh1 = bh[nf >> 1][(nf & 1) * 2 + 1];
                    uint32_t bl0 = bl[nf >> 1][(nf & 1) * 2], bl1 = bl[nf >> 1][(nf & 1) * 2 + 1];
                    mma_bf16(acc[mt][nf], ah[mt], bh0, bh1);
                    mma_bf16(acc[mt][nf], ah[mt], bl0, bl1);
                    mma_bf16(acc[mt][nf], al[mt], bh0, bh1);
                }
        }
        __syncthreads();
    }

    #pragma unroll
    for (int mt = 0; mt < 4; ++mt)
        #pragma unroll
        for (int nf = 0; nf < 4; ++nf) {
            int row0 = m0 + wm * 64 + mt * 16 + (lane >> 2);
            int col  = n0 + wn * 32 + nf * 8 + (lane & 3) * 2;
            *(float2*)&g_h[(size_t)row0 * OUTD + col] =
                make_float2(acc[mt][nf][0], acc[mt][nf][1]);
            *(float2*)&g_h[(size_t)(row0 + 8) * OUTD + col] =
                make_float2(acc[mt][nf][2], acc[mt][nf][3]);
        }

    float* red = (float*)sAh;
    #pragma unroll
    for (int mt = 0; mt < 4; ++mt) {
        float r1a = 0.f, r2a = 0.f, r1b = 0.f, r2b = 0.f;
        #pragma unroll
        for (int nf = 0; nf < 4; ++nf) {
            int col = n0 + wn * 32 + nf * 8 + (lane & 3) * 2;
            float a10 = a1[col], a11 = a1[col + 1];
            float a20 = a2[col], a21 = a2[col + 1];
            r1a += acc[mt][nf][0] * a10 + acc[mt][nf][1] * a11;
            r2a += acc[mt][nf][0] * a20 + acc[mt][nf][1] * a21;
            r1b += acc[mt][nf][2] * a10 + acc[mt][nf][3] * a11;
            r2b += acc[mt][nf][2] * a20 + acc[mt][nf][3] * a21;
        }
        #pragma unroll
        for (int o = 1; o <= 2; o <<= 1) {
            r1a += __shfl_xor_sync(0xFFFFFFFFu, r1a, o);
            r2a += __shfl_xor_sync(0xFFFFFFFFu, r2a, o);
            r1b += __shfl_xor_sync(0xFFFFFFFFu, r1b, o);
            r2b += __shfl_xor_sync(0xFFFFFFFFu, r2b, o);
        }
        if ((lane & 3) == 0) {
            int row = wm * 64 + mt * 16 + (lane >> 2);
            red[row * 4 + wn]             = r1a;
            red[512 + row * 4 + wn]       = r2a;
            red[(row + 8) * 4 + wn]       = r1b;
            red[512 + (row + 8) * 4 + wn] = r2b;
        }
    }
    __syncthreads();
    if (tid < 128) {
        float s1 = red[tid * 4] + red[tid * 4 + 1] + red[tid * 4 + 2] + red[tid * 4 + 3];
        float s2 = red[512 + tid * 4] + red[512 + tid * 4 + 1]
                 + red[512 + tid * 4 + 2] + red[512 + tid * 4 + 3];
        g_s1p[nb * N + m0 + tid] = s1;
        g_s2p[nb * N + m0 + tid] = s2;
    }
}

// ==================== 8-CTA cluster bitonic sort (double-buffered DSMEM) ====================
#define CLUSTER_SYNC() do {                                             \
    asm volatile("barrier.cluster.arrive.aligned;" ::: "memory");       \
    asm volatile("barrier.cluster.wait.aligned;" ::: "memory");         \
} while (0)

__device__ __forceinline__ unsigned long long dsmem_ld64(uint32_t laddr, uint32_t rank) {
    uint32_t ra;
    unsigned long long v;
    asm volatile("mapa.shared::cluster.u32 %0, %1, %2;" : "=r"(ra) : "r"(laddr), "r"(rank));
    asm volatile("ld.shared::cluster.u64 %0, [%1];" : "=l"(v) : "r"(ra) : "memory");
    return v;
}
__device__ __forceinline__ unsigned long long u64min(unsigned long long a, unsigned long long b) { return a < b ? a : b; }
__device__ __forceinline__ unsigned long long u64max(unsigned long long a, unsigned long long b) { return a < b ? b : a; }

__global__ void __launch_bounds__(1024, 1) __cluster_dims__(8, 1, 1) sort_kernel() {
    __shared__ unsigned long long sbuf[2][1024];
    const int t = threadIdx.x;
    uint32_t rank;
    asm("mov.u32 %0, %%cluster_ctarank;" : "=r"(rank));
    const int ge = (int)rank * 1024 + t;

    uint32_t u = __float_as_uint(g_s1p[ge] + g_s1p[N + ge]);
    u ^= (u & 0x80000000u) ? 0xFFFFFFFFu : 0x80000000u;
    unsigned long long own = ((unsigned long long)u << 13) | (unsigned)ge;

    // sizes 2..32: pure shuffles
    #pragma unroll
    for (int size = 2; size <= 32; size <<= 1) {
        bool up = ((ge & size) == 0);
        #pragma unroll
        for (int stride = size >> 1; stride >= 1; stride >>= 1) {
            unsigned long long p = __shfl_xor_sync(0xFFFFFFFFu, own, stride);
            bool keepmin = (((t & stride) == 0) == up);
            own = keepmin ? u64min(own, p) : u64max(own, p);
        }
    }
    int cur = 0;
    unsigned long long* s = sbuf[0];
    s[t] = own;
    __syncthreads();

    // sizes 64..1024: smem strides 32..512, shuffles below
    for (int size = 64; size <= 1024; size <<= 1) {
        for (int stride = size >> 1; stride >= 32; stride >>= 1) {
            if (t < 512) {
                int a = ((t & ~(stride - 1)) << 1) | (t & (stride - 1));
                int b = a + stride;
                bool up = ((((int)rank * 1024 + a) & size) == 0);
                unsigned long long x = s[a], y = s[b];
                if ((x > y) == up) { s[a] = y; s[b] = x; }
            }
            __syncthreads();
        }
        own = s[t];
        bool up = ((ge & size) == 0);
        #pragma unroll
        for (int stride = 16; stride >= 1; stride >>= 1) {
            unsigned long long p = __shfl_xor_sync(0xFFFFFFFFu, own, stride);
            bool keepmin = (((t & stride) == 0) == up);
            own = keepmin ? u64min(own, p) : u64max(own, p);
        }
        s[t] = own;
        __syncthreads();
    }

    CLUSTER_SYNC();   // all CTAs' buffer 0 valid

    const uint32_t addr0 = smem_u32(&sbuf[0][t]);
    const uint32_t addr1 = smem_u32(&sbuf[1][t]);
    for (int size = 2048; size <= 8192; size <<= 1) {
        bool up = ((ge & size) == 0);
        // cross-CTA stages: read cur (own + remote), write alt, single sync, flip
        for (int stride = size >> 1; stride >= 1024; stride >>= 1) {
            unsigned long long mine = sbuf[cur][t];
            unsigned long long other = dsmem_ld64(cur ? addr1 : addr0,
                                                  rank ^ (uint32_t)(stride >> 10));
            bool keepmin = (((ge & stride) == 0) == up);
            sbuf[cur ^ 1][t] = keepmin ? u64min(mine, other) : u64max(mine, other);
            CLUSTER_SYNC();
            cur ^= 1;
        }
        s = sbuf[cur];
        // within-CTA smem stages
        for (int stride = 512; stride >= 32; stride >>= 1) {
            if (t < 512) {
                int a = ((t & ~(stride - 1)) << 1) | (t & (stride - 1));
                int b = a + stride;
                unsigned long long x = s[a], y = s[b];
                if ((x > y) == up) { s[a] = y; s[b] = x; }
            }
            __syncthreads();
        }
        own = s[t];
        #pragma unroll
        for (int stride = 16; stride >= 1; stride >>= 1) {
            unsigned long long p = __shfl_xor_sync(0xFFFFFFFFu, own, stride);
            bool keepmin = (((t & stride) == 0) == up);
            own = keepmin ? u64min(own, p) : u64max(own, p);
        }
        s[t] = own;
        __syncthreads();
        CLUSTER_SYNC();   // cur buffer consistent cluster-wide before next size
    }

    int idx = (int)(own & 0x1FFFu);
    uint32_t uu = (uint32_t)(own >> 13);
    uu ^= (uu & 0x80000000u) ? 0x80000000u : 0xFFFFFFFFu;
    g_key[ge] = __uint_as_float(uu);
    g_idx[ge] = idx;
}

// ==================== wspart: within-chunk partial scans + chunk sums ====================
__global__ void __launch_bounds__(288) wspart_kernel() {
    __shared__ float sh[CHL][OUTD];    // 16 KB
    __shared__ float sw1[CHL], sw2[CHL];
    const int c = blockIdx.x;
    const int k = threadIdx.x;

    if (k < CHL) {
        float m1 = g_key[N - 1];
        float d = g_key[c * CHL + k] - m1;
        sw1[k] = __expf(d);
        sw2[k] = __expf(LRELU_ALPHA * d);
    }
    for (int e = k; e < CHL * OUTD; e += 288) {
        int r = e >> 8, col = e & 255;
        sh[r][col] = g_h[(size_t)g_idx[c * CHL + r] * OUTD + col];
    }
    __syncthreads();

    if (k >= W257) return;

    float acc = 0.f;
    #pragma unroll 4
    for (int r = 0; r < CHL; ++r) {
        int p = c * CHL + r;
        g_P2[(size_t)p * W257 + k] = acc;
        float v = (k < OUTD) ? sh[r][k] : 1.0f;
        acc += sw2[r] * v;
    }
    g_cs2[k * NCH + c] = acc;
    if (c == NCH - 1) g_P2[(size_t)N * W257 + k] = acc;

    acc = 0.f;
    #pragma unroll 4
    for (int r = CHL - 1; r >= 0; --r) {
        int p = c * CHL + r;
        float v = (k < OUTD) ? sh[r][k] : 1.0f;
        acc += sw1[r] * v;
        g_SE[(size_t)p * W257 + k] = acc;
    }
    g_cs1[k * NCH + c] = acc;
    if (c == NCH - 1) g_SE[(size_t)N * W257 + k] = 0.f;
}

// ==================== chunkscan: exclusive offsets, transposed out ====================
__global__ void chunkscan_kernel() {
    int k = blockIdx.x;       // 0..256
    int t = threadIdx.x;      // 0..511
    int lane = t & 31, w = t >> 5;
    float a = g_cs2[k * NCH + t];
    float b = g_cs1[k * NCH + (NCH - 1 - t)];
    float ia = a, ib = b;
    #pragma unroll
    for (int o = 1; o < 32; o <<= 1) {
        float pa = __shfl_up_sync(0xFFFFFFFFu, ia, o);
        float pb = __shfl_up_sync(0xFFFFFFFFu, ib, o);
        if (lane >= o) { ia += pa; ib += pb; }
    }
    __shared__ float wa[16], wb[16];
    if (lane == 31) { wa[w] = ia; wb[w] = ib; }
    __syncthreads();
    if (t < 16) {
        float xa = wa[t], xb = wb[t];
        #pragma unroll
        for (int o = 1; o < 16; o <<= 1) {
            float pa = __shfl_up_sync(0xFFFFu, xa, o);
            float pb = __shfl_up_sync(0xFFFFu, xb, o);
            if (t >= o) { xa += pa; xb += pb; }
        }
        wa[t] = xa; wb[t] = xb;
    }
    __syncthreads();
    float offa = w ? wa[w - 1] : 0.f;
    float offb = w ? wb[w - 1] : 0.f;
    g_co2t[(size_t)t * W257 + k]             = ia - a + offa;   // exclusive prefix offset
    g_co1t[(size_t)(NCH - 1 - t) * W257 + k] = ib - b + offb;   // exclusive suffix offset
}

// ==================== epilogue: 32 rows per block, PDL overlap with chunkscan ====================
__global__ void __launch_bounds__(256) out_kernel(float* __restrict__ out) {
    __shared__ float skey[N];          // 32 KB
    __shared__ int   sp[32];
    __shared__ float sr[32];
    const int tid = threadIdx.x;
    const int rb  = blockIdx.x * 32;

    // Prologue: depends only on sort (g_key) + gemm (g_s2p), both complete
    // before chunkscan started (wspart->chunkscan is serialized).
    #pragma unroll
    for (int i = 0; i < N / 4 / 256; ++i) {
        int e = (i * 256 + tid) * 4;
        *(float4*)&skey[e] = *(const float4*)&g_key[e];
    }
    __syncthreads();

    if (tid < 32) {
        int i = rb + tid;
        float m1 = skey[N - 1];
        float s2 = g_s2p[i] + g_s2p[N + i];
        float t = -s2;
        int lo = 0, hi = N;
        #pragma unroll
        for (int it = 0; it < 13; ++it) {
            int mid = (lo + hi) >> 1;
            if (skey[mid] > t) hi = mid; else lo = mid + 1;
        }
        sp[tid] = lo;
        sr[tid] = __expf((LRELU_ALPHA - 1.0f) * (s2 + m1));
    }
    __syncthreads();

    // Fence: g_co1t / g_co2t come from chunkscan (the PDL-primary).
#if __CUDA_ARCH__ >= 900
    cudaGridDependencySynchronize();
#endif

    #pragma unroll 4
    for (int rr = 0; rr < 32; ++rr) {
        int p = sp[rr];
        int c = p >> 4;                 // CHL = 16
        if (c > NCH - 1) c = NCH - 1;   // p == N clamps to last chunk
        size_t basep = (size_t)p * W257;
        size_t basec = (size_t)c * W257;
        float r = sr[rr];
        float seN = g_SE[basep + OUTD] + g_co1t[basec + OUTD];
        float p2N = g_P2[basep + OUTD] + g_co2t[basec + OUTD];
        float den = seN + r * p2N;
        float se  = g_SE[basep + tid] + g_co1t[basec + tid];
        float p2  = g_P2[basep + tid] + g_co2t[basec + tid];
        out[(size_t)(rb + rr) * OUTD + tid] = (se + r * p2) / den;
    }
}

// ==================== launch ====================
extern "C" void kernel_launch(void* const* d_in, const int* in_sizes, int n_in,
                              void* d_out, int out_size) {
    const float* x  = (const float*)d_in[0];
    const float* Wm = (const float*)d_in[2];
    const float* a1 = (const float*)d_in[3];
    const float* a2 = (const float*)d_in[4];
    float* out = (float*)d_out;

    gemm_fused_kernel<<<dim3(2, 64), 256>>>(x, Wm, a1, a2);
    sort_kernel<<<8, 1024>>>();
    wspart_kernel<<<NCH, 288>>>();
    chunkscan_kernel<<<W257, 512>>>();

    // out_kernel: programmatic stream serialization — may begin its prologue
    // (key staging + binary search) while chunkscan is still running; the
    // device-side cudaGridDependencySynchronize() fences the co1t/co2t reads.
    cudaLaunchConfig_t cfg = {};
    cfg.gridDim  = dim3(N / 32);
    cfg.blockDim = dim3(256);
    cudaLaunchAttribute attrs[1];
    attrs[0].id = cudaLaunchAttributeProgrammaticStreamSerialization;
    attrs[0].val.programmaticStreamSerializationAllowed = 1;
    cfg.attrs = attrs;
    cfg.numAttrs = 1;
    cudaLaunchKernelEx(&cfg, out_kernel, out);
}

// round 17
// speedup vs baseline: 1.9107x; 1.0235x over previous
#include <cuda_runtime.h>
#include <cuda_bf16.h>
#include <cstdint>

#define LRELU_ALPHA 0.2f

constexpr int N    = 8192;
constexpr int KIN  = 512;
constexpr int OUTD = 256;
constexpr int W257 = OUTD + 1;
constexpr int NCH  = 512;
constexpr int CHL  = N / NCH;    // 16

// ---------------- scratch (device globals; no allocation) ----------------
__device__ float g_h[N * OUTD];
__device__ float g_s1p[2 * N];
__device__ float g_s2p[2 * N];
__device__ float g_key[N];
__device__ int   g_idx[N];
__device__ float g_cs1[W257 * NCH];          // chunk sums [k][c]
__device__ float g_cs2[W257 * NCH];
__device__ float g_co1t[NCH * W257];         // exclusive suffix offsets, [c][k]
__device__ float g_co2t[NCH * W257];         // exclusive prefix offsets, [c][k]
__device__ float g_SE[(N + 1) * W257];       // within-chunk partial suffix
__device__ float g_P2[(N + 1) * W257];       // within-chunk partial prefix

__device__ __forceinline__ uint32_t smem_u32(const void* p) {
    uint32_t a;
    asm("{ .reg .u64 t; cvta.to.shared.u64 t, %1; cvt.u32.u64 %0, t; }" : "=r"(a) : "l"(p));
    return a;
}
__device__ __forceinline__ void grid_dep_sync() {
#if __CUDA_ARCH__ >= 900
    cudaGridDependencySynchronize();
#endif
}

// ==================== fused GEMM: h = x @ W^T, + s1/s2 partials ====================
constexpr int SSTR = 40;

__device__ __forceinline__ void ldsm_x4(uint32_t (&r)[4], uint32_t addr) {
    asm volatile("ldmatrix.sync.aligned.m8n8.x4.shared.b16 {%0,%1,%2,%3}, [%4];"
                 : "=r"(r[0]), "=r"(r[1]), "=r"(r[2]), "=r"(r[3]) : "r"(addr));
}
__device__ __forceinline__ void mma_bf16(float (&c)[4], const uint32_t (&a)[4],
                                         uint32_t b0, uint32_t b1) {
    asm volatile(
        "mma.sync.aligned.m16n8k16.row.col.f32.bf16.bf16.f32 "
        "{%0,%1,%2,%3}, {%4,%5,%6,%7}, {%8,%9}, {%0,%1,%2,%3};"
        : "+f"(c[0]), "+f"(c[1]), "+f"(c[2]), "+f"(c[3])
        : "r"(a[0]), "r"(a[1]), "r"(a[2]), "r"(a[3]), "r"(b0), "r"(b1));
}
__device__ __forceinline__ void cvt_hilo(float4 v, uint2& hi, uint2& lo) {
    __nv_bfloat16 h0 = __float2bfloat16(v.x), h1 = __float2bfloat16(v.y);
    __nv_bfloat16 h2 = __float2bfloat16(v.z), h3 = __float2bfloat16(v.w);
    __nv_bfloat16 l0 = __float2bfloat16(v.x - __bfloat162float(h0));
    __nv_bfloat16 l1 = __float2bfloat16(v.y - __bfloat162float(h1));
    __nv_bfloat16 l2 = __float2bfloat16(v.z - __bfloat162float(h2));
    __nv_bfloat16 l3 = __float2bfloat16(v.w - __bfloat162float(h3));
    __nv_bfloat162 p0(h0, h1), p1(h2, h3), q0(l0, l1), q1(l2, l3);
    hi.x = *reinterpret_cast<uint32_t*>(&p0);
    hi.y = *reinterpret_cast<uint32_t*>(&p1);
    lo.x = *reinterpret_cast<uint32_t*>(&q0);
    lo.y = *reinterpret_cast<uint32_t*>(&q1);
}

__global__ void __launch_bounds__(256, 1) gemm_fused_kernel(
    const float* __restrict__ x, const float* __restrict__ Wm,
    const float* __restrict__ a1, const float* __restrict__ a2) {
    __shared__ __nv_bfloat16 sAh[128 * SSTR];
    __shared__ __nv_bfloat16 sAl[128 * SSTR];
    __shared__ __nv_bfloat16 sBh[128 * SSTR];
    __shared__ __nv_bfloat16 sBl[128 * SSTR];

    const int tid  = threadIdx.x;
    const int wid  = tid >> 5;
    const int lane = tid & 31;
    const int wm   = wid & 1;
    const int wn   = wid >> 1;
    const int nb   = blockIdx.x;
    const int m0   = blockIdx.y * 128;
    const int n0   = nb * 128;

    const uint32_t bAh = smem_u32(sAh);
    const uint32_t bAl = smem_u32(sAl);
    const uint32_t bBh = smem_u32(sBh);
    const uint32_t bBl = smem_u32(sBl);

    int srow[4], scol[4];
    #pragma unroll
    for (int i = 0; i < 4; ++i) {
        int lin = i * 256 + tid;
        srow[i] = lin >> 3;
        scol[i] = (lin & 7) * 4;
    }

    float acc[4][4][4] = {};
    float4 pvx[4], pvw[4];

    #pragma unroll
    for (int i = 0; i < 4; ++i) {
        pvx[i] = *(const float4*)(x  + (size_t)(m0 + srow[i]) * KIN + scol[i]);
        pvw[i] = *(const float4*)(Wm + (size_t)(n0 + srow[i]) * KIN + scol[i]);
    }

    for (int kc = 0; kc < KIN / 32; ++kc) {
        #pragma unroll
        for (int i = 0; i < 4; ++i) {
            uint2 hi, lo;
            int so = srow[i] * SSTR + scol[i];
            cvt_hilo(pvx[i], hi, lo);
            *(uint2*)(sAh + so) = hi;
            *(uint2*)(sAl + so) = lo;
            cvt_hilo(pvw[i], hi, lo);
            *(uint2*)(sBh + so) = hi;
            *(uint2*)(sBl + so) = lo;
        }
        __syncthreads();

        if (kc + 1 < KIN / 32) {
            int kb = (kc + 1) * 32;
            #pragma unroll
            for (int i = 0; i < 4; ++i) {
                pvx[i] = *(const float4*)(x  + (size_t)(m0 + srow[i]) * KIN + kb + scol[i]);
                pvw[i] = *(const float4*)(Wm + (size_t)(n0 + srow[i]) * KIN + kb + scol[i]);
            }
        }

        #pragma unroll
        for (int kk = 0; kk < 2; ++kk) {
            uint32_t ah[4][4], al[4][4], bh[2][4], bl[2][4];
            #pragma unroll
            for (int mt = 0; mt < 4; ++mt) {
                uint32_t off = (uint32_t)((wm * 64 + mt * 16 + (lane & 15)) * SSTR
                                          + kk * 16 + (lane >> 4) * 8) * 2;
                ldsm_x4(ah[mt], bAh + off);
                ldsm_x4(al[mt], bAl + off);
            }
            #pragma unroll
            for (int ntp = 0; ntp < 2; ++ntp) {
                uint32_t off = (uint32_t)((wn * 32 + ntp * 16 + ((lane >> 4) * 8) + (lane & 7)) * SSTR
                                          + kk * 16 + ((lane >> 3) & 1) * 8) * 2;
                ldsm_x4(bh[ntp], bBh + off);
                ldsm_x4(bl[ntp], bBl + off);
            }
            #pragma unroll
            for (int mt = 0; mt < 4; ++mt)
                #pragma unroll
                for (int nf = 0; nf < 4; ++nf) {
                    uint32_t bh0 = bh[nf >> 1][(nf & 1) * 2], bh1 = bh[nf >> 1][(nf & 1) * 2 + 1];
                    uint32_t bl0 = bl[nf >> 1][(nf & 1) * 2], bl1 = bl[nf >> 1][(nf & 1) * 2 + 1];
                    mma_bf16(acc[mt][nf], ah[mt], bh0, bh1);
                    mma_bf16(acc[mt][nf], ah[mt], bl0, bl1);
                    mma_bf16(acc[mt][nf], al[mt], bh0, bh1);
                }
        }
        __syncthreads();
    }

    #pragma unroll
    for (int mt = 0; mt < 4; ++mt)
        #pragma unroll
        for (int nf = 0; nf < 4; ++nf) {
            int row0 = m0 + wm * 64 + mt * 16 + (lane >> 2);
            int col  = n0 + wn * 32 + nf * 8 + (lane & 3) * 2;
            *(float2*)&g_h[(size_t)row0 * OUTD + col] =
                make_float2(acc[mt][nf][0], acc[mt][nf][1]);
            *(float2*)&g_h[(size_t)(row0 + 8) * OUTD + col] =
                make_float2(acc[mt][nf][2], acc[mt][nf][3]);
        }

    float* red = (float*)sAh;
    #pragma unroll
    for (int mt = 0; mt < 4; ++mt) {
        float r1a = 0.f, r2a = 0.f, r1b = 0.f, r2b = 0.f;
        #pragma unroll
        for (int nf = 0; nf < 4; ++nf) {
            int col = n0 + wn * 32 + nf * 8 + (lane & 3) * 2;
            float a10 = a1[col], a11 = a1[col + 1];
            float a20 = a2[col], a21 = a2[col + 1];
            r1a += acc[mt][nf][0] * a10 + acc[mt][nf][1] * a11;
            r2a += acc[mt][nf][0] * a20 + acc[mt][nf][1] * a21;
            r1b += acc[mt][nf][2] * a10 + acc[mt][nf][3] * a11;
            r2b += acc[mt][nf][2] * a20 + acc[mt][nf][3] * a21;
        }
        #pragma unroll
        for (int o = 1; o <= 2; o <<= 1) {
            r1a += __shfl_xor_sync(0xFFFFFFFFu, r1a, o);
            r2a += __shfl_xor_sync(0xFFFFFFFFu, r2a, o);
            r1b += __shfl_xor_sync(0xFFFFFFFFu, r1b, o);
            r2b += __shfl_xor_sync(0xFFFFFFFFu, r2b, o);
        }
        if ((lane & 3) == 0) {
            int row = wm * 64 + mt * 16 + (lane >> 2);
            red[row * 4 + wn]             = r1a;
            red[512 + row * 4 + wn]       = r2a;
            red[(row + 8) * 4 + wn]       = r1b;
            red[512 + (row + 8) * 4 + wn] = r2b;
        }
    }
    __syncthreads();
    if (tid < 128) {
        float s1 = red[tid * 4] + red[tid * 4 + 1] + red[tid * 4 + 2] + red[tid * 4 + 3];
        float s2 = red[512 + tid * 4] + red[512 + tid * 4 + 1]
                 + red[512 + tid * 4 + 2] + red[512 + tid * 4 + 3];
        g_s1p[nb * N + m0 + tid] = s1;
        g_s2p[nb * N + m0 + tid] = s2;
    }
}

// ==================== 8-CTA cluster bitonic sort (double-buffered DSMEM) ====================
#define CLUSTER_SYNC() do {                                             \
    asm volatile("barrier.cluster.arrive.aligned;" ::: "memory");       \
    asm volatile("barrier.cluster.wait.aligned;" ::: "memory");         \
} while (0)

__device__ __forceinline__ unsigned long long dsmem_ld64(uint32_t laddr, uint32_t rank) {
    uint32_t ra;
    unsigned long long v;
    asm volatile("mapa.shared::cluster.u32 %0, %1, %2;" : "=r"(ra) : "r"(laddr), "r"(rank));
    asm volatile("ld.shared::cluster.u64 %0, [%1];" : "=l"(v) : "r"(ra) : "memory");
    return v;
}
__device__ __forceinline__ unsigned long long u64min(unsigned long long a, unsigned long long b) { return a < b ? a : b; }
__device__ __forceinline__ unsigned long long u64max(unsigned long long a, unsigned long long b) { return a < b ? b : a; }

__global__ void __launch_bounds__(1024, 1) __cluster_dims__(8, 1, 1) sort_kernel() {
    __shared__ unsigned long long sbuf[2][1024];
    const int t = threadIdx.x;
    uint32_t rank;
    asm("mov.u32 %0, %%cluster_ctarank;" : "=r"(rank));
    const int ge = (int)rank * 1024 + t;

    grid_dep_sync();   // PDL fence: g_s1p from gemm

    uint32_t u = __float_as_uint(g_s1p[ge] + g_s1p[N + ge]);
    u ^= (u & 0x80000000u) ? 0xFFFFFFFFu : 0x80000000u;
    unsigned long long own = ((unsigned long long)u << 13) | (unsigned)ge;

    // sizes 2..32: pure shuffles
    #pragma unroll
    for (int size = 2; size <= 32; size <<= 1) {
        bool up = ((ge & size) == 0);
        #pragma unroll
        for (int stride = size >> 1; stride >= 1; stride >>= 1) {
            unsigned long long p = __shfl_xor_sync(0xFFFFFFFFu, own, stride);
            bool keepmin = (((t & stride) == 0) == up);
            own = keepmin ? u64min(own, p) : u64max(own, p);
        }
    }
    int cur = 0;
    unsigned long long* s = sbuf[0];
    s[t] = own;
    __syncthreads();

    // sizes 64..1024: smem strides 32..512, shuffles below
    for (int size = 64; size <= 1024; size <<= 1) {
        for (int stride = size >> 1; stride >= 32; stride >>= 1) {
            if (t < 512) {
                int a = ((t & ~(stride - 1)) << 1) | (t & (stride - 1));
                int b = a + stride;
                bool up = ((((int)rank * 1024 + a) & size) == 0);
                unsigned long long x = s[a], y = s[b];
                if ((x > y) == up) { s[a] = y; s[b] = x; }
            }
            __syncthreads();
        }
        own = s[t];
        bool up = ((ge & size) == 0);
        #pragma unroll
        for (int stride = 16; stride >= 1; stride >>= 1) {
            unsigned long long p = __shfl_xor_sync(0xFFFFFFFFu, own, stride);
            bool keepmin = (((t & stride) == 0) == up);
            own = keepmin ? u64min(own, p) : u64max(own, p);
        }
        s[t] = own;
        __syncthreads();
    }

    CLUSTER_SYNC();   // all CTAs' buffer 0 valid

    const uint32_t addr0 = smem_u32(&sbuf[0][t]);
    const uint32_t addr1 = smem_u32(&sbuf[1][t]);
    for (int size = 2048; size <= 8192; size <<= 1) {
        bool up = ((ge & size) == 0);
        // cross-CTA stages: read cur (own + remote), write alt, single sync, flip
        for (int stride = size >> 1; stride >= 1024; stride >>= 1) {
            unsigned long long mine = sbuf[cur][t];
            unsigned long long other = dsmem_ld64(cur ? addr1 : addr0,
                                                  rank ^ (uint32_t)(stride >> 10));
            bool keepmin = (((ge & stride) == 0) == up);
            sbuf[cur ^ 1][t] = keepmin ? u64min(mine, other) : u64max(mine, other);
            CLUSTER_SYNC();
            cur ^= 1;
        }
        s = sbuf[cur];
        // within-CTA smem stages
        for (int stride = 512; stride >= 32; stride >>= 1) {
            if (t < 512) {
                int a = ((t & ~(stride - 1)) << 1) | (t & (stride - 1));
                int b = a + stride;
                unsigned long long x = s[a], y = s[b];
                if ((x > y) == up) { s[a] = y; s[b] = x; }
            }
            __syncthreads();
        }
        own = s[t];
        #pragma unroll
        for (int stride = 16; stride >= 1; stride >>= 1) {
            unsigned long long p = __shfl_xor_sync(0xFFFFFFFFu, own, stride);
            bool keepmin = (((t & stride) == 0) == up);
            own = keepmin ? u64min(own, p) : u64max(own, p);
        }
        s[t] = own;
        __syncthreads();
        CLUSTER_SYNC();   // cur buffer consistent cluster-wide before next size
    }

    int idx = (int)(own & 0x1FFFu);
    uint32_t uu = (uint32_t)(own >> 13);
    uu ^= (uu & 0x80000000u) ? 0x80000000u : 0xFFFFFFFFu;
    g_key[ge] = __uint_as_float(uu);
    g_idx[ge] = idx;
}

// ==================== wspart: within-chunk partial scans + chunk sums ====================
__global__ void __launch_bounds__(288) wspart_kernel() {
    __shared__ float sh[CHL][OUTD];    // 16 KB
    __shared__ float sw1[CHL], sw2[CHL];
    const int c = blockIdx.x;
    const int k = threadIdx.x;

    grid_dep_sync();   // PDL fence: g_key/g_idx from sort (g_h from gemm, transitively done)

    if (k < CHL) {
        float m1 = g_key[N - 1];
        float d = g_key[c * CHL + k] - m1;
        sw1[k] = __expf(d);
        sw2[k] = __expf(LRELU_ALPHA * d);
    }
    for (int e = k; e < CHL * OUTD; e += 288) {
        int r = e >> 8, col = e & 255;
        sh[r][col] = g_h[(size_t)g_idx[c * CHL + r] * OUTD + col];
    }
    __syncthreads();

    if (k >= W257) return;

    float acc = 0.f;
    #pragma unroll 4
    for (int r = 0; r < CHL; ++r) {
        int p = c * CHL + r;
        g_P2[(size_t)p * W257 + k] = acc;
        float v = (k < OUTD) ? sh[r][k] : 1.0f;
        acc += sw2[r] * v;
    }
    g_cs2[k * NCH + c] = acc;
    if (c == NCH - 1) g_P2[(size_t)N * W257 + k] = acc;

    acc = 0.f;
    #pragma unroll 4
    for (int r = CHL - 1; r >= 0; --r) {
        int p = c * CHL + r;
        float v = (k < OUTD) ? sh[r][k] : 1.0f;
        acc += sw1[r] * v;
        g_SE[(size_t)p * W257 + k] = acc;
    }
    g_cs1[k * NCH + c] = acc;
    if (c == NCH - 1) g_SE[(size_t)N * W257 + k] = 0.f;
}

// ==================== chunkscan: exclusive offsets, transposed out ====================
__global__ void chunkscan_kernel() {
    int k = blockIdx.x;       // 0..256
    int t = threadIdx.x;      // 0..511
    int lane = t & 31, w = t >> 5;

    grid_dep_sync();   // PDL fence: g_cs1/g_cs2 from wspart

    float a = g_cs2[k * NCH + t];
    float b = g_cs1[k * NCH + (NCH - 1 - t)];
    float ia = a, ib = b;
    #pragma unroll
    for (int o = 1; o < 32; o <<= 1) {
        float pa = __shfl_up_sync(0xFFFFFFFFu, ia, o);
        float pb = __shfl_up_sync(0xFFFFFFFFu, ib, o);
        if (lane >= o) { ia += pa; ib += pb; }
    }
    __shared__ float wa[16], wb[16];
    if (lane == 31) { wa[w] = ia; wb[w] = ib; }
    __syncthreads();
    if (t < 16) {
        float xa = wa[t], xb = wb[t];
        #pragma unroll
        for (int o = 1; o < 16; o <<= 1) {
            float pa = __shfl_up_sync(0xFFFFu, xa, o);
            float pb = __shfl_up_sync(0xFFFFu, xb, o);
            if (t >= o) { xa += pa; xb += pb; }
        }
        wa[t] = xa; wb[t] = xb;
    }
    __syncthreads();
    float offa = w ? wa[w - 1] : 0.f;
    float offb = w ? wb[w - 1] : 0.f;
    g_co2t[(size_t)t * W257 + k]             = ia - a + offa;   // exclusive prefix offset
    g_co1t[(size_t)(NCH - 1 - t) * W257 + k] = ib - b + offb;   // exclusive suffix offset
}

// ==================== epilogue: 32 rows per block, PDL overlap with chunkscan ====================
__global__ void __launch_bounds__(256) out_kernel(float* __restrict__ out) {
    __shared__ float skey[N];          // 32 KB
    __shared__ int   sp[32];
    __shared__ float sr[32];
    const int tid = threadIdx.x;
    const int rb  = blockIdx.x * 32;

    // Prologue: depends only on sort (g_key) + gemm (g_s2p), both complete
    // before chunkscan started (wspart->chunkscan is serialized).
    #pragma unroll
    for (int i = 0; i < N / 4 / 256; ++i) {
        int e = (i * 256 + tid) * 4;
        *(float4*)&skey[e] = *(const float4*)&g_key[e];
    }
    __syncthreads();

    if (tid < 32) {
        int i = rb + tid;
        float m1 = skey[N - 1];
        float s2 = g_s2p[i] + g_s2p[N + i];
        float t = -s2;
        int lo = 0, hi = N;
        #pragma unroll
        for (int it = 0; it < 13; ++it) {
            int mid = (lo + hi) >> 1;
            if (skey[mid] > t) hi = mid; else lo = mid + 1;
        }
        sp[tid] = lo;
        sr[tid] = __expf((LRELU_ALPHA - 1.0f) * (s2 + m1));
    }
    __syncthreads();

    grid_dep_sync();   // PDL fence: g_co1t/g_co2t from chunkscan

    #pragma unroll 4
    for (int rr = 0; rr < 32; ++rr) {
        int p = sp[rr];
        int c = p >> 4;                 // CHL = 16
        if (c > NCH - 1) c = NCH - 1;   // p == N clamps to last chunk
        size_t basep = (size_t)p * W257;
        size_t basec = (size_t)c * W257;
        float r = sr[rr];
        float seN = g_SE[basep + OUTD] + g_co1t[basec + OUTD];
        float p2N = g_P2[basep + OUTD] + g_co2t[basec + OUTD];
        float den = seN + r * p2N;
        float se  = g_SE[basep + tid] + g_co1t[basec + tid];
        float p2  = g_P2[basep + tid] + g_co2t[basec + tid];
        out[(size_t)(rb + rr) * OUTD + tid] = (se + r * p2) / den;
    }
}

// ==================== launch ====================
static inline void launch_pdl(void* fn, dim3 grid, dim3 block, void** args) {
    cudaLaunchConfig_t cfg = {};
    cfg.gridDim  = grid;
    cfg.blockDim = block;
    cudaLaunchAttribute attrs[1];
    attrs[0].id = cudaLaunchAttributeProgrammaticStreamSerialization;
    attrs[0].val.programmaticStreamSerializationAllowed = 1;
    cfg.attrs = attrs;
    cfg.numAttrs = 1;
    cudaLaunchKernelExC(&cfg, fn, args);
}

extern "C" void kernel_launch(void* const* d_in, const int* in_sizes, int n_in,
                              void* d_out, int out_size) {
    const float* x  = (const float*)d_in[0];
    const float* Wm = (const float*)d_in[2];
    const float* a1 = (const float*)d_in[3];
    const float* a2 = (const float*)d_in[4];
    float* out = (float*)d_out;

    gemm_fused_kernel<<<dim3(2, 64), 256>>>(x, Wm, a1, a2);

    void* noargs[] = { nullptr };
    launch_pdl((void*)sort_kernel, dim3(8), dim3(1024), noargs);
    launch_pdl((void*)wspart_kernel, dim3(NCH), dim3(288), noargs);
    launch_pdl((void*)chunkscan_kernel, dim3(W257), dim3(512), noargs);

    void* outargs[] = { (void*)&out };
    launch_pdl((void*)out_kernel, dim3(N / 32), dim3(256), outargs);
}